// round 5
// baseline (speedup 1.0000x reference)
#include <cuda_runtime.h>
#include <cuda_bf16.h>
#include <math.h>
#include <stdint.h>

// ---------------------------------------------------------------------------
// Scratch (no allocation allowed)
// ---------------------------------------------------------------------------
#define MAX_TBD (2048*16*1024)
#define MAX_HALL ((2048+1)*16*1024)
__device__ float g_delta[MAX_TBD];
__device__ float g_cand[MAX_TBD];
__device__ float g_hall[MAX_HALL];              // fallback if d_out holds only outs
__device__ signed char g_xq1[MAX_TBD], g_xq2[MAX_TBD];     // x int8 limbs
__device__ signed char g_hq1[MAX_TBD], g_hq2[MAX_TBD];     // h int8 limbs
__device__ signed char g_wq1[2*1024*1024], g_wq2[2*1024*1024];  // [W_delta;W_x]
__device__ signed char g_woq1[1024*1024], g_woq2[1024*1024];    // W_out
__device__ float g_sx[32768], g_sh[32768], g_sw[2048], g_swo[1024];

// ---------------------------------------------------------------------------
// Helpers
// ---------------------------------------------------------------------------
__device__ __forceinline__ uint32_t smem_u32(const void* p) {
    uint32_t a;
    asm("{ .reg .u64 t; cvta.to.shared.u64 t, %1; cvt.u32.u64 %0, t; }" : "=r"(a) : "l"(p));
    return a;
}

#define LDSM_X4(r0, r1, r2, r3, addr) \
    asm volatile("ldmatrix.sync.aligned.m8n8.x4.shared.b16 {%0,%1,%2,%3}, [%4];" \
                 : "=r"(r0), "=r"(r1), "=r"(r2), "=r"(r3) : "r"(addr))

#define IMMA(c, a, b0, b1) \
    asm volatile("mma.sync.aligned.m16n8k32.row.col.s32.s8.s8.s32 " \
                 "{%0,%1,%2,%3},{%4,%5,%6,%7},{%8,%9},{%0,%1,%2,%3};" \
                 : "+r"((c)[0]), "+r"((c)[1]), "+r"((c)[2]), "+r"((c)[3]) \
                 : "r"((a)[0]), "r"((a)[1]), "r"((a)[2]), "r"((a)[3]), \
                   "r"(b0), "r"(b1))

#define CP16(dst, src) \
    asm volatile("cp.async.cg.shared.global [%0], [%1], 16;" :: "r"(dst), "l"(src) : "memory")
#define CP_COMMIT() asm volatile("cp.async.commit_group;" ::: "memory")
#define CP_WAIT1()  asm volatile("cp.async.wait_group 1;" ::: "memory")
#define CP_WAIT0()  asm volatile("cp.async.wait_group 0;" ::: "memory")

// ---------------------------------------------------------------------------
// Rowwise 2-limb int8 quantization: a = s*(128*A1 + A2) + eps, |eps| <= 0.5*s
// s = rowmax/16256 ; A1 in [-127,127], A2 in [-64,64].
// One block (256 thr) per row.
// ---------------------------------------------------------------------------
__global__ void quant_rows(const float* __restrict__ src,
                           signed char* __restrict__ q1,
                           signed char* __restrict__ q2,
                           float* __restrict__ scales, int K)
{
    const int row = blockIdx.x;
    const float4* sp = (const float4*)(src + (size_t)row * K);
    const int K4 = K >> 2;
    float mx = 0.f;
    for (int i = threadIdx.x; i < K4; i += blockDim.x) {
        float4 f = sp[i];
        mx = fmaxf(mx, fmaxf(fmaxf(fabsf(f.x), fabsf(f.y)),
                             fmaxf(fabsf(f.z), fabsf(f.w))));
    }
    __shared__ float wmax[8];
#pragma unroll
    for (int s = 16; s; s >>= 1) mx = fmaxf(mx, __shfl_xor_sync(~0u, mx, s));
    if ((threadIdx.x & 31) == 0) wmax[threadIdx.x >> 5] = mx;
    __syncthreads();
    float bm = wmax[0];
#pragma unroll
    for (int w = 1; w < 8; ++w) bm = fmaxf(bm, wmax[w]);
    const float inv = bm > 0.f ? 16256.0f / bm : 0.f;
    if (threadIdx.x == 0) scales[row] = bm * (1.0f / 16256.0f);

    char4* p1 = (char4*)(q1 + (size_t)row * K);
    char4* p2 = (char4*)(q2 + (size_t)row * K);
    for (int i = threadIdx.x; i < K4; i += blockDim.x) {
        float4 f = sp[i];
        float q0 = f.x * inv, q1f = f.y * inv, q2f = f.z * inv, q3 = f.w * inv;
        float h0 = rintf(q0 * 0.0078125f), h1 = rintf(q1f * 0.0078125f);
        float h2 = rintf(q2f * 0.0078125f), h3 = rintf(q3 * 0.0078125f);
        char4 a, r;
        a.x = (signed char)(int)h0; a.y = (signed char)(int)h1;
        a.z = (signed char)(int)h2; a.w = (signed char)(int)h3;
        r.x = (signed char)(int)rintf(q0  - 128.f * h0);
        r.y = (signed char)(int)rintf(q1f - 128.f * h1);
        r.z = (signed char)(int)rintf(q2f - 128.f * h2);
        r.w = (signed char)(int)rintf(q3  - 128.f * h3);
        p1[i] = a; p2[i] = r;
    }
}

// ---------------------------------------------------------------------------
// INT8 IMMA GEMM: C = epi( A[M,K] @ B[N,K]^T ), 2-limb int8 (3 passes, lo*lo
// dropped), fp32 combine in epilogue: s_a*s_b*(16384*D11 + 128*(D12+D21)).
// CTA 128x128, 8 warps (2x4), warp tile 64x32, BK=64 bytes.
// cp.async 2-stage pipeline, 80B padded smem rows.
// MODE 0: n < nSplit -> sigmoid(acc+bias0) -> out0 ; else acc+bias1 -> out1
// MODE 1: compete(hsrc) * silu(acc) -> out0 (softmax per 32-col group = warp tile)
// ---------------------------------------------------------------------------
#define STG_A2 10240
#define STG_B1 20480
#define STG_B2 30720
#define STAGE_SZ 40960
#define GSMEM (2 * STAGE_SZ)

template <int MODE>
__global__ void __launch_bounds__(256) gemm_i8(
    const signed char* __restrict__ Aq1,
    const signed char* __restrict__ Aq2,
    const signed char* __restrict__ Bq1,
    const signed char* __restrict__ Bq2,
    const float* __restrict__ sA,
    const float* __restrict__ sB,
    const float* __restrict__ bias0,
    const float* __restrict__ bias1,
    float* __restrict__ out0,
    float* __restrict__ out1,
    const float* __restrict__ hsrc,
    int K, int ldC, int nSplit)
{
    extern __shared__ __align__(1024) char smem[];
    const uint32_t sb = smem_u32(smem);
    const int tid = threadIdx.x, wid = tid >> 5, lid = tid & 31;
    const int m0 = blockIdx.y * 128;
    const int n0 = blockIdx.x * 128;

    // cp.async mapping: thread -> row tid/2, 32B half (tid&1)
    const size_t aOff = (size_t)(m0 + (tid >> 1)) * K + (size_t)(tid & 1) * 32;
    const size_t bOff = (size_t)(n0 + (tid >> 1)) * K + (size_t)(tid & 1) * 32;
    const uint32_t dOff = (uint32_t)(tid >> 1) * 80 + (uint32_t)(tid & 1) * 32;

    const int wm = wid >> 2, wn = wid & 3;
    const uint32_t aoff = ((uint32_t)((lid & 7) + ((lid >> 3) & 1) * 8) + (uint32_t)wm * 64) * 80
                        + (uint32_t)(lid >> 4) * 16;
    const uint32_t boff = ((uint32_t)((lid & 7) + (lid >> 4) * 8) + (uint32_t)wn * 32) * 80
                        + (uint32_t)((lid >> 3) & 1) * 16;

    int acch[4][4][4], accl[4][4][4];
#pragma unroll
    for (int i = 0; i < 4; ++i)
#pragma unroll
        for (int j = 0; j < 4; ++j)
#pragma unroll
            for (int q = 0; q < 4; ++q) { acch[i][j][q] = 0; accl[i][j][q] = 0; }

    const int NCH = K / 64;

    auto issue = [&](int ch, int s) {
        const uint32_t stb = sb + (uint32_t)s * STAGE_SZ;
        const size_t ko = (size_t)ch * 64;
        const signed char* a1 = Aq1 + aOff + ko;
        const signed char* a2 = Aq2 + aOff + ko;
        const signed char* b1 = Bq1 + bOff + ko;
        const signed char* b2 = Bq2 + bOff + ko;
        uint32_t d = stb + dOff;
        CP16(d,                a1);  CP16(d + 16,                a1 + 16);
        CP16(d + STG_A2,       a2);  CP16(d + STG_A2 + 16,       a2 + 16);
        CP16(d + STG_B1,       b1);  CP16(d + STG_B1 + 16,       b1 + 16);
        CP16(d + STG_B2,       b2);  CP16(d + STG_B2 + 16,       b2 + 16);
    };

    issue(0, 0);
    CP_COMMIT();

#pragma unroll 1
    for (int ch = 0; ch < NCH; ++ch) {
        const int s = ch & 1;
        if (ch + 1 < NCH) { issue(ch + 1, s ^ 1); CP_COMMIT(); CP_WAIT1(); }
        else              { CP_WAIT0(); }
        __syncthreads();

        const uint32_t stA = sb + (uint32_t)s * STAGE_SZ;
#pragma unroll
        for (int kk = 0; kk < 2; ++kk) {
            const uint32_t kof = (uint32_t)kk * 32;
            uint32_t b1f[4][2], b2f[4][2];
#pragma unroll
            for (int p = 0; p < 2; ++p) {
                LDSM_X4(b1f[2*p][0], b1f[2*p][1], b1f[2*p+1][0], b1f[2*p+1][1],
                        stA + STG_B1 + boff + (uint32_t)p * 1280 + kof);
                LDSM_X4(b2f[2*p][0], b2f[2*p][1], b2f[2*p+1][0], b2f[2*p+1][1],
                        stA + STG_B2 + boff + (uint32_t)p * 1280 + kof);
            }
#pragma unroll
            for (int mi = 0; mi < 4; ++mi) {
                uint32_t a1[4], a2[4];
                LDSM_X4(a1[0], a1[1], a1[2], a1[3],
                        stA + aoff + (uint32_t)mi * 1280 + kof);
                LDSM_X4(a2[0], a2[1], a2[2], a2[3],
                        stA + STG_A2 + aoff + (uint32_t)mi * 1280 + kof);
#pragma unroll
                for (int nj = 0; nj < 4; ++nj) IMMA(acch[mi][nj], a1, b1f[nj][0], b1f[nj][1]);
#pragma unroll
                for (int nj = 0; nj < 4; ++nj) IMMA(accl[mi][nj], a1, b2f[nj][0], b2f[nj][1]);
#pragma unroll
                for (int nj = 0; nj < 4; ++nj) IMMA(accl[mi][nj], a2, b1f[nj][0], b1f[nj][1]);
            }
        }
        __syncthreads();
    }

    // ---- epilogue ----
    const int qr = lid >> 2;       // 0..7
    const int qc = 2 * (lid & 3);  // 0,2,4,6
    const int gcol0 = n0 + wn * 32;

    float sbv[8];
#pragma unroll
    for (int nj = 0; nj < 4; ++nj) {
        float2 t = *(const float2*)(sB + gcol0 + nj * 8 + qc);
        sbv[2*nj] = t.x; sbv[2*nj+1] = t.y;
    }

    if (MODE == 0) {
        const int sel = (n0 >= nSplit);
        const float* bias = sel ? bias1 : bias0;
        float* Cout = sel ? out1 : out0;
        const int colBase = gcol0 - sel * nSplit;
        float bv[8];
#pragma unroll
        for (int nj = 0; nj < 4; ++nj) {
            float2 t = *(const float2*)(bias + colBase + nj * 8 + qc);
            bv[2*nj] = t.x; bv[2*nj+1] = t.y;
        }
#pragma unroll
        for (int mi = 0; mi < 4; ++mi) {
            const int r0 = m0 + wm * 64 + mi * 16 + qr;
            const float sa0 = sA[r0], sa1 = sA[r0 + 8];
#pragma unroll
            for (int nj = 0; nj < 4; ++nj) {
                const int c = colBase + nj * 8 + qc;
                float v0 = fmaf(16384.f, (float)acch[mi][nj][0], 128.f * (float)accl[mi][nj][0]) * sa0 * sbv[2*nj]   + bv[2*nj];
                float v1 = fmaf(16384.f, (float)acch[mi][nj][1], 128.f * (float)accl[mi][nj][1]) * sa0 * sbv[2*nj+1] + bv[2*nj+1];
                float v2 = fmaf(16384.f, (float)acch[mi][nj][2], 128.f * (float)accl[mi][nj][2]) * sa1 * sbv[2*nj]   + bv[2*nj];
                float v3 = fmaf(16384.f, (float)acch[mi][nj][3], 128.f * (float)accl[mi][nj][3]) * sa1 * sbv[2*nj+1] + bv[2*nj+1];
                if (!sel) {
                    v0 = 1.f / (1.f + __expf(-v0));
                    v1 = 1.f / (1.f + __expf(-v1));
                    v2 = 1.f / (1.f + __expf(-v2));
                    v3 = 1.f / (1.f + __expf(-v3));
                }
                *(float2*)(Cout + (size_t)r0 * ldC + c)       = make_float2(v0, v1);
                *(float2*)(Cout + (size_t)(r0 + 8) * ldC + c) = make_float2(v2, v3);
            }
        }
    } else {
#pragma unroll
        for (int mi = 0; mi < 4; ++mi) {
            const int r0 = m0 + wm * 64 + mi * 16 + qr;
            const int r1 = r0 + 8;
            const float sa0 = sA[r0], sa1 = sA[r1];
            float h0v[8], h1v[8];
#pragma unroll
            for (int nj = 0; nj < 4; ++nj) {
                const int c = gcol0 + nj * 8 + qc;
                float2 t0 = *(const float2*)(hsrc + (size_t)r0 * ldC + c);
                float2 t1 = *(const float2*)(hsrc + (size_t)r1 * ldC + c);
                h0v[2*nj] = t0.x; h0v[2*nj+1] = t0.y;
                h1v[2*nj] = t1.x; h1v[2*nj+1] = t1.y;
            }
            float mx0 = h0v[0], mx1 = h1v[0];
#pragma unroll
            for (int k = 1; k < 8; ++k) {
                mx0 = fmaxf(mx0, h0v[k]);
                mx1 = fmaxf(mx1, h1v[k]);
            }
            mx0 = fmaxf(mx0, __shfl_xor_sync(0xffffffffu, mx0, 1));
            mx0 = fmaxf(mx0, __shfl_xor_sync(0xffffffffu, mx0, 2));
            mx1 = fmaxf(mx1, __shfl_xor_sync(0xffffffffu, mx1, 1));
            mx1 = fmaxf(mx1, __shfl_xor_sync(0xffffffffu, mx1, 2));
            float s0 = 0.f, s1 = 0.f;
#pragma unroll
            for (int k = 0; k < 8; ++k) {
                h0v[k] = __expf(h0v[k] - mx0); s0 += h0v[k];
                h1v[k] = __expf(h1v[k] - mx1); s1 += h1v[k];
            }
            s0 += __shfl_xor_sync(0xffffffffu, s0, 1);
            s0 += __shfl_xor_sync(0xffffffffu, s0, 2);
            s1 += __shfl_xor_sync(0xffffffffu, s1, 1);
            s1 += __shfl_xor_sync(0xffffffffu, s1, 2);
            const float inv0 = 1.f / s0, inv1 = 1.f / s1;
#pragma unroll
            for (int nj = 0; nj < 4; ++nj) {
                const int c = gcol0 + nj * 8 + qc;
                float y0 = fmaf(16384.f, (float)acch[mi][nj][0], 128.f * (float)accl[mi][nj][0]) * sa0 * sbv[2*nj];
                float y1 = fmaf(16384.f, (float)acch[mi][nj][1], 128.f * (float)accl[mi][nj][1]) * sa0 * sbv[2*nj+1];
                float y2 = fmaf(16384.f, (float)acch[mi][nj][2], 128.f * (float)accl[mi][nj][2]) * sa1 * sbv[2*nj];
                float y3 = fmaf(16384.f, (float)acch[mi][nj][3], 128.f * (float)accl[mi][nj][3]) * sa1 * sbv[2*nj+1];
                float v0 = (h0v[2*nj]   * inv0) * (y0 / (1.f + __expf(-y0)));
                float v1 = (h0v[2*nj+1] * inv0) * (y1 / (1.f + __expf(-y1)));
                float v2 = (h1v[2*nj]   * inv1) * (y2 / (1.f + __expf(-y2)));
                float v3 = (h1v[2*nj+1] * inv1) * (y3 / (1.f + __expf(-y3)));
                *(float2*)(out0 + (size_t)r0 * ldC + c) = make_float2(v0, v1);
                *(float2*)(out0 + (size_t)r1 * ldC + c) = make_float2(v2, v3);
            }
        }
    }
}

// ---------------------------------------------------------------------------
// Diagonal scan: 16384 independent lanes, register double-buffered
// ---------------------------------------------------------------------------
__global__ void scan_kernel(const float* __restrict__ delta,
                            const float* __restrict__ cand,
                            const float* __restrict__ h0,
                            const float* __restrict__ r_h,
                            float* __restrict__ h_all,
                            int T, int BD, int D)
{
    int lane = blockIdx.x * blockDim.x + threadIdx.x;
    if (lane >= BD) return;

    float h = h0[lane];
    float rh = r_h[lane % D];
    h_all[lane] = h;

    const float* dp = delta + lane;
    const float* cp = cand + lane;
    float* hp = h_all + BD + lane;

    const int U = 8;
    int nG = T / U;
    float db[2][U], cb[2][U];
#pragma unroll
    for (int u = 0; u < U; ++u) {
        db[0][u] = dp[(size_t)u * BD];
        cb[0][u] = cp[(size_t)u * BD];
    }
    int buf = 0;
    for (int g = 0; g < nG; ++g) {
        int nbuf = buf ^ 1;
        if (g + 1 < nG) {
            size_t base = (size_t)(g + 1) * U * BD;
#pragma unroll
            for (int u = 0; u < U; ++u) {
                db[nbuf][u] = dp[base + (size_t)u * BD];
                cb[nbuf][u] = cp[base + (size_t)u * BD];
            }
        }
        size_t ob = (size_t)g * U * BD;
#pragma unroll
        for (int u = 0; u < U; ++u) {
            float d = db[buf][u], c = cb[buf][u];
            float cv = tanhf(fmaf(rh, h, c));
            h = fmaf(d, cv - h, h);
            hp[ob + (size_t)u * BD] = h;
        }
        buf = nbuf;
    }
    for (int t = nG * U; t < T; ++t) {
        float d = dp[(size_t)t * BD], c = cp[(size_t)t * BD];
        float cv = tanhf(fmaf(rh, h, c));
        h = fmaf(d, cv - h, h);
        hp[(size_t)t * BD] = h;
    }
}

// ---------------------------------------------------------------------------
extern "C" void kernel_launch(void* const* d_in, const int* in_sizes, int n_in,
                              void* d_out, int out_size)
{
    const float* x       = (const float*)d_in[0];
    const float* h0      = (const float*)d_in[1];
    const float* W_x     = (const float*)d_in[2];
    const float* r_h     = (const float*)d_in[3];
    const float* b       = (const float*)d_in[4];
    const float* W_delta = (const float*)d_in[5];
    const float* b_delta = (const float*)d_in[6];
    const float* W_out   = (const float*)d_in[7];
    float* out = (float*)d_out;

    int D  = (int)(sqrt((double)in_sizes[2]) + 0.5);
    int Bn = in_sizes[1] / D;
    int Tn = in_sizes[0] / (Bn * D);
    int BD = Bn * D;
    int M  = Tn * Bn;
    int DD = D * D;

    float *gd, *gc, *ghall, *sx, *sh, *sw, *swo;
    signed char *xq1, *xq2, *hq1, *hq2, *wq1, *wq2, *woq1, *woq2;
    cudaGetSymbolAddress((void**)&gd,    g_delta);
    cudaGetSymbolAddress((void**)&gc,    g_cand);
    cudaGetSymbolAddress((void**)&ghall, g_hall);
    cudaGetSymbolAddress((void**)&xq1,   g_xq1);
    cudaGetSymbolAddress((void**)&xq2,   g_xq2);
    cudaGetSymbolAddress((void**)&hq1,   g_hq1);
    cudaGetSymbolAddress((void**)&hq2,   g_hq2);
    cudaGetSymbolAddress((void**)&wq1,   g_wq1);
    cudaGetSymbolAddress((void**)&wq2,   g_wq2);
    cudaGetSymbolAddress((void**)&woq1,  g_woq1);
    cudaGetSymbolAddress((void**)&woq2,  g_woq2);
    cudaGetSymbolAddress((void**)&sx,    g_sx);
    cudaGetSymbolAddress((void**)&sh,    g_sh);
    cudaGetSymbolAddress((void**)&sw,    g_sw);
    cudaGetSymbolAddress((void**)&swo,   g_swo);

    float *hall, *outs;
    long need_both = (long)(Tn + 1) * BD + (long)M * D;
    if ((long)out_size >= need_both) {
        hall = out;
        outs = out + (size_t)(Tn + 1) * BD;
    } else {
        hall = ghall;
        outs = out;
    }

    cudaFuncSetAttribute(gemm_i8<0>, cudaFuncAttributeMaxDynamicSharedMemorySize, GSMEM);
    cudaFuncSetAttribute(gemm_i8<1>, cudaFuncAttributeMaxDynamicSharedMemorySize, GSMEM);

    // Phase 0: rowwise int8 2-limb quantization of x and weights
    quant_rows<<<M, 256>>>(x,       xq1,       xq2,       sx,     D);
    quant_rows<<<D, 256>>>(W_delta, wq1,       wq2,       sw,     D);
    quant_rows<<<D, 256>>>(W_x,     wq1 + DD,  wq2 + DD,  sw + D, D);
    quant_rows<<<D, 256>>>(W_out,   woq1,      woq2,      swo,    D);

    // Phase 1: fused delta|cand GEMM (N = 2D, split at D)
    gemm_i8<0><<<dim3(2 * D / 128, M / 128), 256, GSMEM>>>(
        xq1, xq2, wq1, wq2, sx, sw, b_delta, b, gd, gc, nullptr, D, D, D);

    // Phase 2: diagonal scan
    scan_kernel<<<(BD + 127) / 128, 128>>>(gd, gc, h0, r_h, hall, Tn, BD, D);

    // Phase 2b: quantize h rows for the output GEMM
    quant_rows<<<M, 256>>>(hall + BD, hq1, hq2, sh, D);

    // Phase 3: output GEMM with fused compete-softmax + silu epilogue
    gemm_i8<1><<<dim3(D / 128, M / 128), 256, GSMEM>>>(
        hq1, hq2, woq1, woq2, sh, swo, nullptr, nullptr, outs, nullptr,
        hall + BD, D, D, 0);
}

// round 6
// speedup vs baseline: 3.0598x; 3.0598x over previous
#include <cuda_runtime.h>
#include <cuda_fp16.h>
#include <math.h>
#include <stdint.h>

// ---------------------------------------------------------------------------
// Scratch (no allocation allowed)
// ---------------------------------------------------------------------------
#define MAX_TBD (2048*16*1024)
#define MAX_HALL ((2048+1)*16*1024)
__device__ float g_delta[MAX_TBD];
__device__ float g_cand[MAX_TBD];
__device__ float g_hall[MAX_HALL];      // fallback if d_out holds only outs
__device__ __half g_xh[MAX_TBD], g_xl[MAX_TBD];   // x fp16 hi/lo limbs
__device__ __half g_hh[MAX_TBD], g_hl[MAX_TBD];   // h fp16 hi/lo limbs
__device__ __half g_wh[2*1024*1024];              // [W_delta ; W_x] fp16
__device__ __half g_woh[1024*1024];               // W_out fp16

// ---------------------------------------------------------------------------
// Helpers
// ---------------------------------------------------------------------------
__device__ __forceinline__ uint32_t smem_u32(const void* p) {
    uint32_t a;
    asm("{ .reg .u64 t; cvta.to.shared.u64 t, %1; cvt.u32.u64 %0, t; }" : "=r"(a) : "l"(p));
    return a;
}

#define LDSM_X4(r0, r1, r2, r3, addr) \
    asm volatile("ldmatrix.sync.aligned.m8n8.x4.shared.b16 {%0,%1,%2,%3}, [%4];" \
                 : "=r"(r0), "=r"(r1), "=r"(r2), "=r"(r3) : "r"(addr))

#define MMAF16(c, a, b0, b1) \
    asm volatile("mma.sync.aligned.m16n8k16.row.col.f32.f16.f16.f32 " \
                 "{%0,%1,%2,%3},{%4,%5,%6,%7},{%8,%9},{%0,%1,%2,%3};" \
                 : "+f"((c)[0]), "+f"((c)[1]), "+f"((c)[2]), "+f"((c)[3]) \
                 : "r"((a)[0]), "r"((a)[1]), "r"((a)[2]), "r"((a)[3]), \
                   "r"(b0), "r"(b1))

#define CP16(dst, src) \
    asm volatile("cp.async.cg.shared.global [%0], [%1], 16;" :: "r"(dst), "l"(src) : "memory")
#define CP_COMMIT() asm volatile("cp.async.commit_group;" ::: "memory")
#define CP_WAIT1()  asm volatile("cp.async.wait_group 1;" ::: "memory")
#define CP_WAIT0()  asm volatile("cp.async.wait_group 0;" ::: "memory")

// ---------------------------------------------------------------------------
// fp32 -> fp16 RN hi + fp16 RN residual lo (A-side exact 2-limb split)
// ---------------------------------------------------------------------------
__global__ void split_f16(const float* __restrict__ src,
                          __half* __restrict__ hi,
                          __half* __restrict__ lo, int n4)
{
    int i = blockIdx.x * blockDim.x + threadIdx.x;
    if (i >= n4) return;
    float4 f = ((const float4*)src)[i];
    __half h0 = __float2half_rn(f.x), h1 = __float2half_rn(f.y);
    __half h2 = __float2half_rn(f.z), h3 = __float2half_rn(f.w);
    __half l0 = __float2half_rn(f.x - __half2float(h0));
    __half l1 = __float2half_rn(f.y - __half2float(h1));
    __half l2 = __float2half_rn(f.z - __half2float(h2));
    __half l3 = __float2half_rn(f.w - __half2float(h3));
    ((__half2*)hi)[2*i]   = __halves2half2(h0, h1);
    ((__half2*)hi)[2*i+1] = __halves2half2(h2, h3);
    ((__half2*)lo)[2*i]   = __halves2half2(l0, l1);
    ((__half2*)lo)[2*i+1] = __halves2half2(l2, l3);
}

// fp32 -> fp16 RN single limb (weights)
__global__ void cvt_f16(const float* __restrict__ src,
                        __half* __restrict__ dst, int n4)
{
    int i = blockIdx.x * blockDim.x + threadIdx.x;
    if (i >= n4) return;
    float4 f = ((const float4*)src)[i];
    ((__half2*)dst)[2*i]   = __halves2half2(__float2half_rn(f.x), __float2half_rn(f.y));
    ((__half2*)dst)[2*i+1] = __halves2half2(__float2half_rn(f.z), __float2half_rn(f.w));
}

// ---------------------------------------------------------------------------
// fp16 2-pass HMMA GEMM: C = epi( (Ahi+Alo)[M,K] @ B[N,K]^T ), fp32 accum.
// CTA 128x128, 8 warps (2x4), warp tile 64x32, BK=32, cp.async 2-stage.
// Padded smem rows: 32 fp16 (64B) + 16B pad = 80B. Hi-pass MMAs all issue
// before lo-pass re-touches the same accumulators (RAW distance 16).
// MODE 0: n0 <  nSplit -> sigmoid(acc+bias0) -> out0 (delta)
//         n0 >= nSplit ->          acc+bias1 -> out1 (cand)
// MODE 1: compete(hsrc) * silu(acc) -> out0 (softmax per 32-col warp group)
// ---------------------------------------------------------------------------
#define STG_A_LO 10240
#define STG_B    20480
#define STAGE_SZ 30720
#define GSMEM (2 * STAGE_SZ)

template <int MODE>
__global__ void __launch_bounds__(256, 2) gemm_f16(
    const __half* __restrict__ Ahi,
    const __half* __restrict__ Alo,
    const __half* __restrict__ Bh,
    const float* __restrict__ bias0,
    const float* __restrict__ bias1,
    float* __restrict__ out0,
    float* __restrict__ out1,
    const float* __restrict__ hsrc,
    int K, int ldC, int nSplit)
{
    extern __shared__ __align__(1024) char smem[];
    const uint32_t sb = smem_u32(smem);
    const int tid = threadIdx.x, wid = tid >> 5, lid = tid & 31;
    const int m0 = blockIdx.y * 128;
    const int n0 = blockIdx.x * 128;

    // cp.async mapping: thread -> row tid/2, 32B half (tid&1)
    const size_t aOff = (size_t)(m0 + (tid >> 1)) * K + (size_t)(tid & 1) * 16;
    const size_t bOff = (size_t)(n0 + (tid >> 1)) * K + (size_t)(tid & 1) * 16;
    const uint32_t dOff = (uint32_t)(tid >> 1) * 80 + (uint32_t)(tid & 1) * 32;

    const int wm = wid >> 2, wn = wid & 3;
    const uint32_t aoff = ((uint32_t)((lid & 7) + ((lid >> 3) & 1) * 8) + (uint32_t)wm * 64) * 80
                        + (uint32_t)(lid >> 4) * 16;
    const uint32_t boff = ((uint32_t)((lid & 7) + (lid >> 4) * 8) + (uint32_t)wn * 32) * 80
                        + (uint32_t)((lid >> 3) & 1) * 16;

    float acc[4][4][4];
#pragma unroll
    for (int i = 0; i < 4; ++i)
#pragma unroll
        for (int j = 0; j < 4; ++j)
#pragma unroll
            for (int q = 0; q < 4; ++q) acc[i][j][q] = 0.f;

    const int NCH = K / 32;

    auto issue = [&](int ch, int s) {
        const uint32_t stb = sb + (uint32_t)s * STAGE_SZ;
        const size_t ko = (size_t)ch * 32;
        const __half* a1 = Ahi + aOff + ko;
        const __half* a2 = Alo + aOff + ko;
        const __half* b1 = Bh  + bOff + ko;
        uint32_t d = stb + dOff;
        CP16(d,               a1);  CP16(d + 16,               a1 + 8);
        CP16(d + STG_A_LO,    a2);  CP16(d + STG_A_LO + 16,    a2 + 8);
        CP16(d + STG_B,       b1);  CP16(d + STG_B + 16,       b1 + 8);
    };

    issue(0, 0);
    CP_COMMIT();

#pragma unroll 1
    for (int ch = 0; ch < NCH; ++ch) {
        const int s = ch & 1;
        if (ch + 1 < NCH) { issue(ch + 1, s ^ 1); CP_COMMIT(); CP_WAIT1(); }
        else              { CP_WAIT0(); }
        __syncthreads();

        const uint32_t stA = sb + (uint32_t)s * STAGE_SZ;
#pragma unroll
        for (int kk = 0; kk < 2; ++kk) {
            const uint32_t kof = (uint32_t)kk * 32;
            uint32_t bh[4][2];
            LDSM_X4(bh[0][0], bh[0][1], bh[1][0], bh[1][1],
                    stA + STG_B + boff + kof);
            LDSM_X4(bh[2][0], bh[2][1], bh[3][0], bh[3][1],
                    stA + STG_B + boff + 1280 + kof);
            uint32_t ah[4][4], al[4][4];
#pragma unroll
            for (int mi = 0; mi < 4; ++mi)
                LDSM_X4(ah[mi][0], ah[mi][1], ah[mi][2], ah[mi][3],
                        stA + aoff + (uint32_t)mi * 1280 + kof);
#pragma unroll
            for (int mi = 0; mi < 4; ++mi)
                LDSM_X4(al[mi][0], al[mi][1], al[mi][2], al[mi][3],
                        stA + STG_A_LO + aoff + (uint32_t)mi * 1280 + kof);
            // hi pass: 16 independent MMAs
#pragma unroll
            for (int mi = 0; mi < 4; ++mi)
#pragma unroll
                for (int nj = 0; nj < 4; ++nj)
                    MMAF16(acc[mi][nj], ah[mi], bh[nj][0], bh[nj][1]);
            // lo pass: re-touches accumulators at RAW distance 16
#pragma unroll
            for (int mi = 0; mi < 4; ++mi)
#pragma unroll
                for (int nj = 0; nj < 4; ++nj)
                    MMAF16(acc[mi][nj], al[mi], bh[nj][0], bh[nj][1]);
        }
        __syncthreads();
    }

    // ---- epilogue ----
    const int qr = lid >> 2;       // 0..7
    const int qc = 2 * (lid & 3);  // 0,2,4,6
    const int gcol0 = n0 + wn * 32;

    if (MODE == 0) {
        const int sel = (n0 >= nSplit);
        const float* bias = sel ? bias1 : bias0;
        float* Cout = sel ? out1 : out0;
        const int colBase = gcol0 - sel * nSplit;
        float bv[8];
#pragma unroll
        for (int nj = 0; nj < 4; ++nj) {
            float2 t = *(const float2*)(bias + colBase + nj * 8 + qc);
            bv[2*nj] = t.x; bv[2*nj+1] = t.y;
        }
#pragma unroll
        for (int mi = 0; mi < 4; ++mi) {
            const int r0 = m0 + wm * 64 + mi * 16 + qr;
#pragma unroll
            for (int nj = 0; nj < 4; ++nj) {
                const int c = colBase + nj * 8 + qc;
                float v0 = acc[mi][nj][0] + bv[2*nj];
                float v1 = acc[mi][nj][1] + bv[2*nj+1];
                float v2 = acc[mi][nj][2] + bv[2*nj];
                float v3 = acc[mi][nj][3] + bv[2*nj+1];
                if (!sel) {
                    v0 = 1.f / (1.f + __expf(-v0));
                    v1 = 1.f / (1.f + __expf(-v1));
                    v2 = 1.f / (1.f + __expf(-v2));
                    v3 = 1.f / (1.f + __expf(-v3));
                }
                *(float2*)(Cout + (size_t)r0 * ldC + c)       = make_float2(v0, v1);
                *(float2*)(Cout + (size_t)(r0 + 8) * ldC + c) = make_float2(v2, v3);
            }
        }
    } else {
#pragma unroll
        for (int mi = 0; mi < 4; ++mi) {
            const int r0 = m0 + wm * 64 + mi * 16 + qr;
            const int r1 = r0 + 8;
            float h0v[8], h1v[8];
#pragma unroll
            for (int nj = 0; nj < 4; ++nj) {
                const int c = gcol0 + nj * 8 + qc;
                float2 t0 = *(const float2*)(hsrc + (size_t)r0 * ldC + c);
                float2 t1 = *(const float2*)(hsrc + (size_t)r1 * ldC + c);
                h0v[2*nj] = t0.x; h0v[2*nj+1] = t0.y;
                h1v[2*nj] = t1.x; h1v[2*nj+1] = t1.y;
            }
            float mx0 = h0v[0], mx1 = h1v[0];
#pragma unroll
            for (int k = 1; k < 8; ++k) {
                mx0 = fmaxf(mx0, h0v[k]);
                mx1 = fmaxf(mx1, h1v[k]);
            }
            mx0 = fmaxf(mx0, __shfl_xor_sync(0xffffffffu, mx0, 1));
            mx0 = fmaxf(mx0, __shfl_xor_sync(0xffffffffu, mx0, 2));
            mx1 = fmaxf(mx1, __shfl_xor_sync(0xffffffffu, mx1, 1));
            mx1 = fmaxf(mx1, __shfl_xor_sync(0xffffffffu, mx1, 2));
            float s0 = 0.f, s1 = 0.f;
#pragma unroll
            for (int k = 0; k < 8; ++k) {
                h0v[k] = __expf(h0v[k] - mx0); s0 += h0v[k];
                h1v[k] = __expf(h1v[k] - mx1); s1 += h1v[k];
            }
            s0 += __shfl_xor_sync(0xffffffffu, s0, 1);
            s0 += __shfl_xor_sync(0xffffffffu, s0, 2);
            s1 += __shfl_xor_sync(0xffffffffu, s1, 1);
            s1 += __shfl_xor_sync(0xffffffffu, s1, 2);
            const float inv0 = 1.f / s0, inv1 = 1.f / s1;
#pragma unroll
            for (int nj = 0; nj < 4; ++nj) {
                const int c = gcol0 + nj * 8 + qc;
                float y0 = acc[mi][nj][0], y1 = acc[mi][nj][1];
                float y2 = acc[mi][nj][2], y3 = acc[mi][nj][3];
                float v0 = (h0v[2*nj]   * inv0) * (y0 / (1.f + __expf(-y0)));
                float v1 = (h0v[2*nj+1] * inv0) * (y1 / (1.f + __expf(-y1)));
                float v2 = (h1v[2*nj]   * inv1) * (y2 / (1.f + __expf(-y2)));
                float v3 = (h1v[2*nj+1] * inv1) * (y3 / (1.f + __expf(-y3)));
                *(float2*)(out0 + (size_t)r0 * ldC + c) = make_float2(v0, v1);
                *(float2*)(out0 + (size_t)r1 * ldC + c) = make_float2(v2, v3);
            }
        }
    }
}

// ---------------------------------------------------------------------------
// Diagonal scan: emits fp32 h_all and fp16 hi/lo split of h[1..T]
// ---------------------------------------------------------------------------
__global__ void scan_kernel(const float* __restrict__ delta,
                            const float* __restrict__ cand,
                            const float* __restrict__ h0,
                            const float* __restrict__ r_h,
                            float* __restrict__ h_all,
                            __half* __restrict__ hhi,
                            __half* __restrict__ hlo,
                            int T, int BD, int D)
{
    int lane = blockIdx.x * blockDim.x + threadIdx.x;
    if (lane >= BD) return;

    float h = h0[lane];
    float rh = r_h[lane % D];
    h_all[lane] = h;

    const float* dp = delta + lane;
    const float* cp = cand + lane;
    float* hp = h_all + BD + lane;
    __half* hip = hhi + lane;
    __half* lop = hlo + lane;

    const int U = 8;
    int nG = T / U;
    float db[2][U], cb[2][U];
#pragma unroll
    for (int u = 0; u < U; ++u) {
        db[0][u] = dp[(size_t)u * BD];
        cb[0][u] = cp[(size_t)u * BD];
    }
    int buf = 0;
    for (int g = 0; g < nG; ++g) {
        int nbuf = buf ^ 1;
        if (g + 1 < nG) {
            size_t base = (size_t)(g + 1) * U * BD;
#pragma unroll
            for (int u = 0; u < U; ++u) {
                db[nbuf][u] = dp[base + (size_t)u * BD];
                cb[nbuf][u] = cp[base + (size_t)u * BD];
            }
        }
        size_t ob = (size_t)g * U * BD;
#pragma unroll
        for (int u = 0; u < U; ++u) {
            float d = db[buf][u], c = cb[buf][u];
            float cv = tanhf(fmaf(rh, h, c));
            h = fmaf(d, cv - h, h);
            size_t idx = ob + (size_t)u * BD;
            hp[idx] = h;
            __half hh = __float2half_rn(h);
            hip[idx] = hh;
            lop[idx] = __float2half_rn(h - __half2float(hh));
        }
        buf = nbuf;
    }
}

// ---------------------------------------------------------------------------
extern "C" void kernel_launch(void* const* d_in, const int* in_sizes, int n_in,
                              void* d_out, int out_size)
{
    const float* x       = (const float*)d_in[0];
    const float* h0      = (const float*)d_in[1];
    const float* W_x     = (const float*)d_in[2];
    const float* r_h     = (const float*)d_in[3];
    const float* b       = (const float*)d_in[4];
    const float* W_delta = (const float*)d_in[5];
    const float* b_delta = (const float*)d_in[6];
    const float* W_out   = (const float*)d_in[7];
    float* out = (float*)d_out;

    int D  = (int)(sqrt((double)in_sizes[2]) + 0.5);
    int Bn = in_sizes[1] / D;
    int Tn = in_sizes[0] / (Bn * D);
    int BD = Bn * D;
    int M  = Tn * Bn;
    int DD = D * D;

    float *gd, *gc, *ghall;
    __half *xh, *xl, *hh, *hl, *wh, *woh;
    cudaGetSymbolAddress((void**)&gd,    g_delta);
    cudaGetSymbolAddress((void**)&gc,    g_cand);
    cudaGetSymbolAddress((void**)&ghall, g_hall);
    cudaGetSymbolAddress((void**)&xh,    g_xh);
    cudaGetSymbolAddress((void**)&xl,    g_xl);
    cudaGetSymbolAddress((void**)&hh,    g_hh);
    cudaGetSymbolAddress((void**)&hl,    g_hl);
    cudaGetSymbolAddress((void**)&wh,    g_wh);
    cudaGetSymbolAddress((void**)&woh,   g_woh);

    float *hall, *outs;
    long need_both = (long)(Tn + 1) * BD + (long)M * D;
    if ((long)out_size >= need_both) {
        hall = out;
        outs = out + (size_t)(Tn + 1) * BD;
    } else {
        hall = ghall;
        outs = out;
    }

    cudaFuncSetAttribute(gemm_f16<0>, cudaFuncAttributeMaxDynamicSharedMemorySize, GSMEM);
    cudaFuncSetAttribute(gemm_f16<1>, cudaFuncAttributeMaxDynamicSharedMemorySize, GSMEM);

    // Phase 0: fp16 conversions
    int n4x = (M * D) / 4;
    int n4w = DD / 4;
    split_f16<<<(n4x + 255) / 256, 256>>>(x, xh, xl, n4x);
    cvt_f16<<<(n4w + 255) / 256, 256>>>(W_delta, wh,      n4w);
    cvt_f16<<<(n4w + 255) / 256, 256>>>(W_x,     wh + DD, n4w);
    cvt_f16<<<(n4w + 255) / 256, 256>>>(W_out,   woh,     n4w);

    // Phase 1: fused delta|cand GEMM (N = 2D, split at D)
    gemm_f16<0><<<dim3(2 * D / 128, M / 128), 256, GSMEM>>>(
        xh, xl, wh, b_delta, b, gd, gc, nullptr, D, D, D);

    // Phase 2: diagonal scan (+ fp16 split of h)
    scan_kernel<<<(BD + 127) / 128, 128>>>(gd, gc, h0, r_h, hall, hh, hl, Tn, BD, D);

    // Phase 3: output GEMM with fused compete-softmax + silu epilogue
    gemm_f16<1><<<dim3(D / 128, M / 128), 256, GSMEM>>>(
        hh, hl, woh, nullptr, nullptr, outs, nullptr, hall + BD, D, D, 0);
}

// round 7
// speedup vs baseline: 4.2629x; 1.3932x over previous
#include <cuda_runtime.h>
#include <cuda_fp16.h>
#include <math.h>
#include <stdint.h>

// ---------------------------------------------------------------------------
// Scratch (no allocation allowed)
// ---------------------------------------------------------------------------
#define MAX_TBD (2048*16*1024)
#define MAX_HALL ((2048+1)*16*1024)
__device__ float g_delta[MAX_TBD];
__device__ float g_cand[MAX_TBD];
__device__ float g_hall[MAX_HALL];      // fallback if d_out holds only outs
__device__ __half g_xh[MAX_TBD];        // x fp16
__device__ __half g_hh[MAX_TBD];        // h fp16 (written by scan)
__device__ __half g_wh[2*1024*1024];    // [W_delta ; W_x] fp16
__device__ __half g_woh[1024*1024];     // W_out fp16

// ---------------------------------------------------------------------------
// Helpers
// ---------------------------------------------------------------------------
__device__ __forceinline__ uint32_t smem_u32(const void* p) {
    uint32_t a;
    asm("{ .reg .u64 t; cvta.to.shared.u64 t, %1; cvt.u32.u64 %0, t; }" : "=r"(a) : "l"(p));
    return a;
}

#define LDSM_X4(r0, r1, r2, r3, addr) \
    asm volatile("ldmatrix.sync.aligned.m8n8.x4.shared.b16 {%0,%1,%2,%3}, [%4];" \
                 : "=r"(r0), "=r"(r1), "=r"(r2), "=r"(r3) : "r"(addr))

#define MMAF16(c, a, b0, b1) \
    asm volatile("mma.sync.aligned.m16n8k16.row.col.f32.f16.f16.f32 " \
                 "{%0,%1,%2,%3},{%4,%5,%6,%7},{%8,%9},{%0,%1,%2,%3};" \
                 : "+f"((c)[0]), "+f"((c)[1]), "+f"((c)[2]), "+f"((c)[3]) \
                 : "r"((a)[0]), "r"((a)[1]), "r"((a)[2]), "r"((a)[3]), \
                   "r"(b0), "r"(b1))

#define CP16(dst, src) \
    asm volatile("cp.async.cg.shared.global [%0], [%1], 16;" :: "r"(dst), "l"(src) : "memory")
#define CP_COMMIT() asm volatile("cp.async.commit_group;" ::: "memory")
#define CP_WAIT2()  asm volatile("cp.async.wait_group 2;" ::: "memory")
#define CP_WAIT1()  asm volatile("cp.async.wait_group 1;" ::: "memory")
#define CP_WAIT0()  asm volatile("cp.async.wait_group 0;" ::: "memory")

// fp32 -> fp16 RN, vectorized x4
__global__ void cvt_f16(const float* __restrict__ src,
                        __half* __restrict__ dst, int n4)
{
    int i = blockIdx.x * blockDim.x + threadIdx.x;
    if (i >= n4) return;
    float4 f = ((const float4*)src)[i];
    ((__half2*)dst)[2*i]   = __halves2half2(__float2half_rn(f.x), __float2half_rn(f.y));
    ((__half2*)dst)[2*i+1] = __halves2half2(__float2half_rn(f.z), __float2half_rn(f.w));
}

// ---------------------------------------------------------------------------
// fp16 1-pass HMMA GEMM: C = epi( A[M,K] @ B[N,K]^T ), fp32 accum.
// CTA 128x128, 8 warps (2x4), warp tile 64x32, BK=32, cp.async 3-stage.
// Padded smem rows: 32 fp16 (64B) + 16B pad = 80B.
// MODE 0: n0 <  nSplit -> sigmoid(acc+bias0) -> out0 (delta)
//         n0 >= nSplit ->          acc+bias1 -> out1 (cand)
// MODE 1: compete(hsrc) * silu(acc) -> out0 (softmax per 32-col warp group)
// ---------------------------------------------------------------------------
#define STG_B    10240
#define STAGE_SZ 20480
#define NSTAGE   3
#define GSMEM (NSTAGE * STAGE_SZ)

template <int MODE>
__global__ void __launch_bounds__(256, 2) gemm_f16(
    const __half* __restrict__ Ah,
    const __half* __restrict__ Bh,
    const float* __restrict__ bias0,
    const float* __restrict__ bias1,
    float* __restrict__ out0,
    float* __restrict__ out1,
    const float* __restrict__ hsrc,
    int K, int ldC, int nSplit)
{
    extern __shared__ __align__(1024) char smem[];
    const uint32_t sb = smem_u32(smem);
    const int tid = threadIdx.x, wid = tid >> 5, lid = tid & 31;
    const int m0 = blockIdx.y * 128;
    const int n0 = blockIdx.x * 128;

    // cp.async mapping: thread -> row tid/2, 32B half (tid&1)
    const size_t aOff = (size_t)(m0 + (tid >> 1)) * K + (size_t)(tid & 1) * 16;
    const size_t bOff = (size_t)(n0 + (tid >> 1)) * K + (size_t)(tid & 1) * 16;
    const uint32_t dOff = (uint32_t)(tid >> 1) * 80 + (uint32_t)(tid & 1) * 32;

    const int wm = wid >> 2, wn = wid & 3;
    const uint32_t aoff = ((uint32_t)((lid & 7) + ((lid >> 3) & 1) * 8) + (uint32_t)wm * 64) * 80
                        + (uint32_t)(lid >> 4) * 16;
    const uint32_t boff = ((uint32_t)((lid & 7) + (lid >> 4) * 8) + (uint32_t)wn * 32) * 80
                        + (uint32_t)((lid >> 3) & 1) * 16;

    float acc[4][4][4];
#pragma unroll
    for (int i = 0; i < 4; ++i)
#pragma unroll
        for (int j = 0; j < 4; ++j)
#pragma unroll
            for (int q = 0; q < 4; ++q) acc[i][j][q] = 0.f;

    const int NCH = K / 32;

    auto issue = [&](int ch, int s) {
        const uint32_t stb = sb + (uint32_t)s * STAGE_SZ;
        const size_t ko = (size_t)ch * 32;
        const __half* a1 = Ah + aOff + ko;
        const __half* b1 = Bh + bOff + ko;
        uint32_t d = stb + dOff;
        CP16(d,            a1);  CP16(d + 16,            a1 + 8);
        CP16(d + STG_B,    b1);  CP16(d + STG_B + 16,    b1 + 8);
    };

    issue(0, 0); CP_COMMIT();
    issue(1, 1); CP_COMMIT();

#pragma unroll 1
    for (int ch = 0; ch < NCH; ++ch) {
        const int s = ch % NSTAGE;
        if (ch + 2 < NCH) {
            issue(ch + 2, (ch + 2) % NSTAGE); CP_COMMIT(); CP_WAIT2();
        } else if (ch + 1 < NCH) {
            CP_WAIT1();
        } else {
            CP_WAIT0();
        }
        __syncthreads();

        const uint32_t stA = sb + (uint32_t)s * STAGE_SZ;
#pragma unroll
        for (int kk = 0; kk < 2; ++kk) {
            const uint32_t kof = (uint32_t)kk * 32;
            uint32_t bh[4][2];
            LDSM_X4(bh[0][0], bh[0][1], bh[1][0], bh[1][1],
                    stA + STG_B + boff + kof);
            LDSM_X4(bh[2][0], bh[2][1], bh[3][0], bh[3][1],
                    stA + STG_B + boff + 1280 + kof);
            uint32_t ah[4][4];
#pragma unroll
            for (int mi = 0; mi < 4; ++mi)
                LDSM_X4(ah[mi][0], ah[mi][1], ah[mi][2], ah[mi][3],
                        stA + aoff + (uint32_t)mi * 1280 + kof);
#pragma unroll
            for (int mi = 0; mi < 4; ++mi)
#pragma unroll
                for (int nj = 0; nj < 4; ++nj)
                    MMAF16(acc[mi][nj], ah[mi], bh[nj][0], bh[nj][1]);
        }
        __syncthreads();
    }

    // ---- epilogue ----
    const int qr = lid >> 2;       // 0..7
    const int qc = 2 * (lid & 3);  // 0,2,4,6
    const int gcol0 = n0 + wn * 32;

    if (MODE == 0) {
        const int sel = (n0 >= nSplit);
        const float* bias = sel ? bias1 : bias0;
        float* Cout = sel ? out1 : out0;
        const int colBase = gcol0 - sel * nSplit;
        float bv[8];
#pragma unroll
        for (int nj = 0; nj < 4; ++nj) {
            float2 t = *(const float2*)(bias + colBase + nj * 8 + qc);
            bv[2*nj] = t.x; bv[2*nj+1] = t.y;
        }
#pragma unroll
        for (int mi = 0; mi < 4; ++mi) {
            const int r0 = m0 + wm * 64 + mi * 16 + qr;
#pragma unroll
            for (int nj = 0; nj < 4; ++nj) {
                const int c = colBase + nj * 8 + qc;
                float v0 = acc[mi][nj][0] + bv[2*nj];
                float v1 = acc[mi][nj][1] + bv[2*nj+1];
                float v2 = acc[mi][nj][2] + bv[2*nj];
                float v3 = acc[mi][nj][3] + bv[2*nj+1];
                if (!sel) {
                    v0 = 1.f / (1.f + __expf(-v0));
                    v1 = 1.f / (1.f + __expf(-v1));
                    v2 = 1.f / (1.f + __expf(-v2));
                    v3 = 1.f / (1.f + __expf(-v3));
                }
                *(float2*)(Cout + (size_t)r0 * ldC + c)       = make_float2(v0, v1);
                *(float2*)(Cout + (size_t)(r0 + 8) * ldC + c) = make_float2(v2, v3);
            }
        }
    } else {
#pragma unroll
        for (int mi = 0; mi < 4; ++mi) {
            const int r0 = m0 + wm * 64 + mi * 16 + qr;
            const int r1 = r0 + 8;
            float h0v[8], h1v[8];
#pragma unroll
            for (int nj = 0; nj < 4; ++nj) {
                const int c = gcol0 + nj * 8 + qc;
                float2 t0 = *(const float2*)(hsrc + (size_t)r0 * ldC + c);
                float2 t1 = *(const float2*)(hsrc + (size_t)r1 * ldC + c);
                h0v[2*nj] = t0.x; h0v[2*nj+1] = t0.y;
                h1v[2*nj] = t1.x; h1v[2*nj+1] = t1.y;
            }
            float mx0 = h0v[0], mx1 = h1v[0];
#pragma unroll
            for (int k = 1; k < 8; ++k) {
                mx0 = fmaxf(mx0, h0v[k]);
                mx1 = fmaxf(mx1, h1v[k]);
            }
            mx0 = fmaxf(mx0, __shfl_xor_sync(0xffffffffu, mx0, 1));
            mx0 = fmaxf(mx0, __shfl_xor_sync(0xffffffffu, mx0, 2));
            mx1 = fmaxf(mx1, __shfl_xor_sync(0xffffffffu, mx1, 1));
            mx1 = fmaxf(mx1, __shfl_xor_sync(0xffffffffu, mx1, 2));
            float s0 = 0.f, s1 = 0.f;
#pragma unroll
            for (int k = 0; k < 8; ++k) {
                h0v[k] = __expf(h0v[k] - mx0); s0 += h0v[k];
                h1v[k] = __expf(h1v[k] - mx1); s1 += h1v[k];
            }
            s0 += __shfl_xor_sync(0xffffffffu, s0, 1);
            s0 += __shfl_xor_sync(0xffffffffu, s0, 2);
            s1 += __shfl_xor_sync(0xffffffffu, s1, 1);
            s1 += __shfl_xor_sync(0xffffffffu, s1, 2);
            const float inv0 = 1.f / s0, inv1 = 1.f / s1;
#pragma unroll
            for (int nj = 0; nj < 4; ++nj) {
                const int c = gcol0 + nj * 8 + qc;
                float y0 = acc[mi][nj][0], y1 = acc[mi][nj][1];
                float y2 = acc[mi][nj][2], y3 = acc[mi][nj][3];
                float v0 = (h0v[2*nj]   * inv0) * (y0 / (1.f + __expf(-y0)));
                float v1 = (h0v[2*nj+1] * inv0) * (y1 / (1.f + __expf(-y1)));
                float v2 = (h1v[2*nj]   * inv1) * (y2 / (1.f + __expf(-y2)));
                float v3 = (h1v[2*nj+1] * inv1) * (y3 / (1.f + __expf(-y3)));
                *(float2*)(out0 + (size_t)r0 * ldC + c) = make_float2(v0, v1);
                *(float2*)(out0 + (size_t)r1 * ldC + c) = make_float2(v2, v3);
            }
        }
    }
}

// ---------------------------------------------------------------------------
// Diagonal scan: emits fp32 h_all and fp16 h[1..T]
// ---------------------------------------------------------------------------
__global__ void scan_kernel(const float* __restrict__ delta,
                            const float* __restrict__ cand,
                            const float* __restrict__ h0,
                            const float* __restrict__ r_h,
                            float* __restrict__ h_all,
                            __half* __restrict__ hhi,
                            int T, int BD, int D)
{
    int lane = blockIdx.x * blockDim.x + threadIdx.x;
    if (lane >= BD) return;

    float h = h0[lane];
    float rh = r_h[lane % D];
    h_all[lane] = h;

    const float* dp = delta + lane;
    const float* cp = cand + lane;
    float* hp = h_all + BD + lane;
    __half* hip = hhi + lane;

    const int U = 8;
    int nG = T / U;
    float db[2][U], cb[2][U];
#pragma unroll
    for (int u = 0; u < U; ++u) {
        db[0][u] = dp[(size_t)u * BD];
        cb[0][u] = cp[(size_t)u * BD];
    }
    int buf = 0;
    for (int g = 0; g < nG; ++g) {
        int nbuf = buf ^ 1;
        if (g + 1 < nG) {
            size_t base = (size_t)(g + 1) * U * BD;
#pragma unroll
            for (int u = 0; u < U; ++u) {
                db[nbuf][u] = dp[base + (size_t)u * BD];
                cb[nbuf][u] = cp[base + (size_t)u * BD];
            }
        }
        size_t ob = (size_t)g * U * BD;
#pragma unroll
        for (int u = 0; u < U; ++u) {
            float d = db[buf][u], c = cb[buf][u];
            float cv = tanhf(fmaf(rh, h, c));
            h = fmaf(d, cv - h, h);
            size_t idx = ob + (size_t)u * BD;
            hp[idx] = h;
            hip[idx] = __float2half_rn(h);
        }
        buf = nbuf;
    }
}

// ---------------------------------------------------------------------------
extern "C" void kernel_launch(void* const* d_in, const int* in_sizes, int n_in,
                              void* d_out, int out_size)
{
    const float* x       = (const float*)d_in[0];
    const float* h0      = (const float*)d_in[1];
    const float* W_x     = (const float*)d_in[2];
    const float* r_h     = (const float*)d_in[3];
    const float* b       = (const float*)d_in[4];
    const float* W_delta = (const float*)d_in[5];
    const float* b_delta = (const float*)d_in[6];
    const float* W_out   = (const float*)d_in[7];
    float* out = (float*)d_out;

    int D  = (int)(sqrt((double)in_sizes[2]) + 0.5);
    int Bn = in_sizes[1] / D;
    int Tn = in_sizes[0] / (Bn * D);
    int BD = Bn * D;
    int M  = Tn * Bn;
    int DD = D * D;

    float *gd, *gc, *ghall;
    __half *xh, *hh, *wh, *woh;
    cudaGetSymbolAddress((void**)&gd,    g_delta);
    cudaGetSymbolAddress((void**)&gc,    g_cand);
    cudaGetSymbolAddress((void**)&ghall, g_hall);
    cudaGetSymbolAddress((void**)&xh,    g_xh);
    cudaGetSymbolAddress((void**)&hh,    g_hh);
    cudaGetSymbolAddress((void**)&wh,    g_wh);
    cudaGetSymbolAddress((void**)&woh,   g_woh);

    float *hall, *outs;
    long need_both = (long)(Tn + 1) * BD + (long)M * D;
    if ((long)out_size >= need_both) {
        hall = out;
        outs = out + (size_t)(Tn + 1) * BD;
    } else {
        hall = ghall;
        outs = out;
    }

    cudaFuncSetAttribute(gemm_f16<0>, cudaFuncAttributeMaxDynamicSharedMemorySize, GSMEM);
    cudaFuncSetAttribute(gemm_f16<1>, cudaFuncAttributeMaxDynamicSharedMemorySize, GSMEM);

    // Phase 0: fp16 conversions
    int n4x = (M * D) / 4;
    int n4w = DD / 4;
    cvt_f16<<<(n4x + 255) / 256, 256>>>(x, xh, n4x);
    cvt_f16<<<(n4w + 255) / 256, 256>>>(W_delta, wh,      n4w);
    cvt_f16<<<(n4w + 255) / 256, 256>>>(W_x,     wh + DD, n4w);
    cvt_f16<<<(n4w + 255) / 256, 256>>>(W_out,   woh,     n4w);

    // Phase 1: fused delta|cand GEMM (N = 2D, split at D)
    gemm_f16<0><<<dim3(2 * D / 128, M / 128), 256, GSMEM>>>(
        xh, wh, b_delta, b, gd, gc, nullptr, D, D, D);

    // Phase 2: diagonal scan (+ fp16 h)
    scan_kernel<<<(BD + 127) / 128, 128>>>(gd, gc, h0, r_h, hall, hh, Tn, BD, D);

    // Phase 3: output GEMM with fused compete-softmax + silu epilogue
    gemm_f16<1><<<dim3(D / 128, M / 128), 256, GSMEM>>>(
        hh, woh, nullptr, nullptr, outs, nullptr, hall + BD, D, D, 0);
}

// round 8
// speedup vs baseline: 5.1359x; 1.2048x over previous
#include <cuda_runtime.h>
#include <cuda_fp16.h>
#include <math.h>
#include <stdint.h>

// ---------------------------------------------------------------------------
// Scratch (no allocation allowed)
// ---------------------------------------------------------------------------
#define MAX_TBD (2048*16*1024)
#define MAX_HALL ((2048+1)*16*1024)
#define MAX_BD   (16*1024)
#define MAX_NCHK 64
__device__ float g_delta[MAX_TBD];
__device__ float g_cand[MAX_TBD];
__device__ float g_hall[MAX_HALL];      // fallback if d_out holds only outs
__device__ __half g_xh[MAX_TBD];        // x fp16
__device__ __half g_hh[MAX_TBD];        // h fp16 (written by scan)
__device__ __half g_wh[2*1024*1024];    // [W_delta ; W_x] fp16
__device__ __half g_woh[1024*1024];     // W_out fp16
__device__ float g_Abuf[MAX_NCHK*MAX_BD];
__device__ float g_Bbuf[MAX_NCHK*MAX_BD];
__device__ float g_hb[MAX_NCHK*MAX_BD];
__device__ int   g_rh_zero;

// ---------------------------------------------------------------------------
// Helpers
// ---------------------------------------------------------------------------
__device__ __forceinline__ uint32_t smem_u32(const void* p) {
    uint32_t a;
    asm("{ .reg .u64 t; cvta.to.shared.u64 t, %1; cvt.u32.u64 %0, t; }" : "=r"(a) : "l"(p));
    return a;
}

#define LDSM_X4(r0, r1, r2, r3, addr) \
    asm volatile("ldmatrix.sync.aligned.m8n8.x4.shared.b16 {%0,%1,%2,%3}, [%4];" \
                 : "=r"(r0), "=r"(r1), "=r"(r2), "=r"(r3) : "r"(addr))

#define MMAF16(c, a, b0, b1) \
    asm volatile("mma.sync.aligned.m16n8k16.row.col.f32.f16.f16.f32 " \
                 "{%0,%1,%2,%3},{%4,%5,%6,%7},{%8,%9},{%0,%1,%2,%3};" \
                 : "+f"((c)[0]), "+f"((c)[1]), "+f"((c)[2]), "+f"((c)[3]) \
                 : "r"((a)[0]), "r"((a)[1]), "r"((a)[2]), "r"((a)[3]), \
                   "r"(b0), "r"(b1))

#define CP16(dst, src) \
    asm volatile("cp.async.cg.shared.global [%0], [%1], 16;" :: "r"(dst), "l"(src) : "memory")
#define CP_COMMIT() asm volatile("cp.async.commit_group;" ::: "memory")
#define CP_WAIT1()  asm volatile("cp.async.wait_group 1;" ::: "memory")
#define CP_WAIT0()  asm volatile("cp.async.wait_group 0;" ::: "memory")

// fp32 -> fp16 RN, vectorized x4
__global__ void cvt_f16(const float* __restrict__ src,
                        __half* __restrict__ dst, int n4)
{
    int i = blockIdx.x * blockDim.x + threadIdx.x;
    if (i >= n4) return;
    float4 f = ((const float4*)src)[i];
    ((__half2*)dst)[2*i]   = __halves2half2(__float2half_rn(f.x), __float2half_rn(f.y));
    ((__half2*)dst)[2*i+1] = __halves2half2(__float2half_rn(f.z), __float2half_rn(f.w));
}

// ---------------------------------------------------------------------------
// fp16 1-pass HMMA GEMM: C = epi( A[M,K] @ B[N,K]^T ), fp32 accum.
// CTA 128x128, 8 warps (2x4), warp tile 64x32, BK=32, cp.async 3-stage ring,
// ONE __syncthreads per chunk (wait -> sync -> issue ch+2 -> compute).
// Padded smem rows: 32 fp16 (64B) + 16B pad = 80B.
// MODE 0: n0 <  nSplit -> sigmoid(acc+bias0) -> out0 (delta)
//         n0 >= nSplit ->          acc+bias1 -> out1 (cand)
// MODE 1: compete(hsrc) * silu(acc) -> out0 (softmax per 32-col warp group)
// ---------------------------------------------------------------------------
#define STG_B    10240
#define STAGE_SZ 20480
#define NSTAGE   3
#define GSMEM (NSTAGE * STAGE_SZ)

template <int MODE>
__global__ void __launch_bounds__(256, 2) gemm_f16(
    const __half* __restrict__ Ah,
    const __half* __restrict__ Bh,
    const float* __restrict__ bias0,
    const float* __restrict__ bias1,
    float* __restrict__ out0,
    float* __restrict__ out1,
    const float* __restrict__ hsrc,
    int K, int ldC, int nSplit)
{
    extern __shared__ __align__(1024) char smem[];
    const uint32_t sb = smem_u32(smem);
    const int tid = threadIdx.x, wid = tid >> 5, lid = tid & 31;
    const int m0 = blockIdx.y * 128;
    const int n0 = blockIdx.x * 128;

    const size_t aOff = (size_t)(m0 + (tid >> 1)) * K + (size_t)(tid & 1) * 16;
    const size_t bOff = (size_t)(n0 + (tid >> 1)) * K + (size_t)(tid & 1) * 16;
    const uint32_t dOff = (uint32_t)(tid >> 1) * 80 + (uint32_t)(tid & 1) * 32;

    const int wm = wid >> 2, wn = wid & 3;
    const uint32_t aoff = ((uint32_t)((lid & 7) + ((lid >> 3) & 1) * 8) + (uint32_t)wm * 64) * 80
                        + (uint32_t)(lid >> 4) * 16;
    const uint32_t boff = ((uint32_t)((lid & 7) + (lid >> 4) * 8) + (uint32_t)wn * 32) * 80
                        + (uint32_t)((lid >> 3) & 1) * 16;

    float acc[4][4][4];
#pragma unroll
    for (int i = 0; i < 4; ++i)
#pragma unroll
        for (int j = 0; j < 4; ++j)
#pragma unroll
            for (int q = 0; q < 4; ++q) acc[i][j][q] = 0.f;

    const int NCH = K / 32;

    auto issue = [&](int ch, int s) {
        const uint32_t stb = sb + (uint32_t)s * STAGE_SZ;
        const size_t ko = (size_t)ch * 32;
        const __half* a1 = Ah + aOff + ko;
        const __half* b1 = Bh + bOff + ko;
        uint32_t d = stb + dOff;
        CP16(d,            a1);  CP16(d + 16,            a1 + 8);
        CP16(d + STG_B,    b1);  CP16(d + STG_B + 16,    b1 + 8);
    };

    issue(0, 0); CP_COMMIT();
    issue(1, 1); CP_COMMIT();

#pragma unroll 1
    for (int ch = 0; ch < NCH; ++ch) {
        const int s = ch % NSTAGE;
        if (ch + 1 < NCH) CP_WAIT1(); else CP_WAIT0();
        __syncthreads();   // stage s ready; stage (ch+2)%3 == (ch-1)%3 drained
        if (ch + 2 < NCH) { issue(ch + 2, (ch + 2) % NSTAGE); CP_COMMIT(); }

        const uint32_t stA = sb + (uint32_t)s * STAGE_SZ;
#pragma unroll
        for (int kk = 0; kk < 2; ++kk) {
            const uint32_t kof = (uint32_t)kk * 32;
            uint32_t bh[4][2];
            LDSM_X4(bh[0][0], bh[0][1], bh[1][0], bh[1][1],
                    stA + STG_B + boff + kof);
            LDSM_X4(bh[2][0], bh[2][1], bh[3][0], bh[3][1],
                    stA + STG_B + boff + 1280 + kof);
            uint32_t ah[4][4];
#pragma unroll
            for (int mi = 0; mi < 4; ++mi)
                LDSM_X4(ah[mi][0], ah[mi][1], ah[mi][2], ah[mi][3],
                        stA + aoff + (uint32_t)mi * 1280 + kof);
#pragma unroll
            for (int mi = 0; mi < 4; ++mi)
#pragma unroll
                for (int nj = 0; nj < 4; ++nj)
                    MMAF16(acc[mi][nj], ah[mi], bh[nj][0], bh[nj][1]);
        }
    }

    // ---- epilogue ----
    const int qr = lid >> 2;       // 0..7
    const int qc = 2 * (lid & 3);  // 0,2,4,6
    const int gcol0 = n0 + wn * 32;

    if (MODE == 0) {
        const int sel = (n0 >= nSplit);
        const float* bias = sel ? bias1 : bias0;
        float* Cout = sel ? out1 : out0;
        const int colBase = gcol0 - sel * nSplit;
        float bv[8];
#pragma unroll
        for (int nj = 0; nj < 4; ++nj) {
            float2 t = *(const float2*)(bias + colBase + nj * 8 + qc);
            bv[2*nj] = t.x; bv[2*nj+1] = t.y;
        }
#pragma unroll
        for (int mi = 0; mi < 4; ++mi) {
            const int r0 = m0 + wm * 64 + mi * 16 + qr;
#pragma unroll
            for (int nj = 0; nj < 4; ++nj) {
                const int c = colBase + nj * 8 + qc;
                float v0 = acc[mi][nj][0] + bv[2*nj];
                float v1 = acc[mi][nj][1] + bv[2*nj+1];
                float v2 = acc[mi][nj][2] + bv[2*nj];
                float v3 = acc[mi][nj][3] + bv[2*nj+1];
                if (!sel) {
                    v0 = 1.f / (1.f + __expf(-v0));
                    v1 = 1.f / (1.f + __expf(-v1));
                    v2 = 1.f / (1.f + __expf(-v2));
                    v3 = 1.f / (1.f + __expf(-v3));
                }
                *(float2*)(Cout + (size_t)r0 * ldC + c)       = make_float2(v0, v1);
                *(float2*)(Cout + (size_t)(r0 + 8) * ldC + c) = make_float2(v2, v3);
            }
        }
    } else {
#pragma unroll
        for (int mi = 0; mi < 4; ++mi) {
            const int r0 = m0 + wm * 64 + mi * 16 + qr;
            const int r1 = r0 + 8;
            float h0v[8], h1v[8];
#pragma unroll
            for (int nj = 0; nj < 4; ++nj) {
                const int c = gcol0 + nj * 8 + qc;
                float2 t0 = *(const float2*)(hsrc + (size_t)r0 * ldC + c);
                float2 t1 = *(const float2*)(hsrc + (size_t)r1 * ldC + c);
                h0v[2*nj] = t0.x; h0v[2*nj+1] = t0.y;
                h1v[2*nj] = t1.x; h1v[2*nj+1] = t1.y;
            }
            float mx0 = h0v[0], mx1 = h1v[0];
#pragma unroll
            for (int k = 1; k < 8; ++k) {
                mx0 = fmaxf(mx0, h0v[k]);
                mx1 = fmaxf(mx1, h1v[k]);
            }
            mx0 = fmaxf(mx0, __shfl_xor_sync(0xffffffffu, mx0, 1));
            mx0 = fmaxf(mx0, __shfl_xor_sync(0xffffffffu, mx0, 2));
            mx1 = fmaxf(mx1, __shfl_xor_sync(0xffffffffu, mx1, 1));
            mx1 = fmaxf(mx1, __shfl_xor_sync(0xffffffffu, mx1, 2));
            float s0 = 0.f, s1 = 0.f;
#pragma unroll
            for (int k = 0; k < 8; ++k) {
                h0v[k] = __expf(h0v[k] - mx0); s0 += h0v[k];
                h1v[k] = __expf(h1v[k] - mx1); s1 += h1v[k];
            }
            s0 += __shfl_xor_sync(0xffffffffu, s0, 1);
            s0 += __shfl_xor_sync(0xffffffffu, s0, 2);
            s1 += __shfl_xor_sync(0xffffffffu, s1, 1);
            s1 += __shfl_xor_sync(0xffffffffu, s1, 2);
            const float inv0 = 1.f / s0, inv1 = 1.f / s1;
#pragma unroll
            for (int nj = 0; nj < 4; ++nj) {
                const int c = gcol0 + nj * 8 + qc;
                float y0 = acc[mi][nj][0], y1 = acc[mi][nj][1];
                float y2 = acc[mi][nj][2], y3 = acc[mi][nj][3];
                float v0 = (h0v[2*nj]   * inv0) * (y0 / (1.f + __expf(-y0)));
                float v1 = (h0v[2*nj+1] * inv0) * (y1 / (1.f + __expf(-y1)));
                float v2 = (h1v[2*nj]   * inv1) * (y2 / (1.f + __expf(-y2)));
                float v3 = (h1v[2*nj+1] * inv1) * (y3 / (1.f + __expf(-y3)));
                *(float2*)(out0 + (size_t)r0 * ldC + c) = make_float2(v0, v1);
                *(float2*)(out0 + (size_t)r1 * ldC + c) = make_float2(v2, v3);
            }
        }
    }
}

// ---------------------------------------------------------------------------
// Scan: parallel fast path when r_h == 0 (linear recurrence), else sequential.
// ---------------------------------------------------------------------------
__global__ void rh_flag_kernel(const float* __restrict__ r_h, int D)
{
    __shared__ int any;
    if (threadIdx.x == 0) any = 0;
    __syncthreads();
    int nz = 0;
    for (int i = threadIdx.x; i < D; i += blockDim.x)
        if (r_h[i] != 0.f) nz = 1;
    if (__syncthreads_or(nz)) { if (threadIdx.x == 0) g_rh_zero = 0; }
    else                      { if (threadIdx.x == 0) g_rh_zero = 1; }
}

// Phase 1: per-chunk affine composition (A,B): h_end = A*h_start + B
__global__ void scan_part1(const float* __restrict__ delta,
                           const float* __restrict__ cand,
                           float* __restrict__ Abuf,
                           float* __restrict__ Bbuf,
                           int BD, int CHK)
{
    if (!g_rh_zero) return;
    const int lane = blockIdx.x * blockDim.x + threadIdx.x;
    const int cc = blockIdx.y;
    const size_t base = (size_t)cc * CHK * BD + lane;
    float A = 1.f, Bv = 0.f;
#pragma unroll 4
    for (int u = 0; u < CHK; ++u) {
        float d = delta[base + (size_t)u * BD];
        float c = cand[base + (size_t)u * BD];
        float a = 1.f - d;
        float b = d * tanhf(c);
        A *= a;
        Bv = fmaf(a, Bv, b);
    }
    Abuf[(size_t)cc * BD + lane] = A;
    Bbuf[(size_t)cc * BD + lane] = Bv;
}

// Phase 2: boundary scan across chunks (NCHK steps)
__global__ void scan_part2(const float* __restrict__ Abuf,
                           const float* __restrict__ Bbuf,
                           const float* __restrict__ h0,
                           float* __restrict__ hb,
                           float* __restrict__ h_all,
                           int BD, int NCHK)
{
    if (!g_rh_zero) return;
    const int lane = blockIdx.x * blockDim.x + threadIdx.x;
    float h = h0[lane];
    h_all[lane] = h;
#pragma unroll 4
    for (int cc = 0; cc < NCHK; ++cc) {
        hb[(size_t)cc * BD + lane] = h;
        h = fmaf(Abuf[(size_t)cc * BD + lane], h, Bbuf[(size_t)cc * BD + lane]);
    }
}

// Phase 3: recompute within chunk from boundary, write h_all fp32 + h fp16
__global__ void scan_part3(const float* __restrict__ delta,
                           const float* __restrict__ cand,
                           const float* __restrict__ hb,
                           float* __restrict__ h_all,
                           __half* __restrict__ hhi,
                           int BD, int CHK)
{
    if (!g_rh_zero) return;
    const int lane = blockIdx.x * blockDim.x + threadIdx.x;
    const int cc = blockIdx.y;
    const size_t base = (size_t)cc * CHK * BD + lane;
    float h = hb[(size_t)cc * BD + lane];
#pragma unroll 4
    for (int u = 0; u < CHK; ++u) {
        float d = delta[base + (size_t)u * BD];
        float c = cand[base + (size_t)u * BD];
        float cv = tanhf(c);
        h = fmaf(d, cv - h, h);
        h_all[BD + base + (size_t)u * BD] = h;
        hhi[base + (size_t)u * BD] = __float2half_rn(h);
    }
}

// Fallback: sequential scan (general r_h) — runs only when g_rh_zero == 0
__global__ void scan_seq(const float* __restrict__ delta,
                         const float* __restrict__ cand,
                         const float* __restrict__ h0,
                         const float* __restrict__ r_h,
                         float* __restrict__ h_all,
                         __half* __restrict__ hhi,
                         int T, int BD, int D)
{
    if (g_rh_zero) return;
    int lane = blockIdx.x * blockDim.x + threadIdx.x;
    if (lane >= BD) return;
    float h = h0[lane];
    float rh = r_h[lane % D];
    h_all[lane] = h;
    const float* dp = delta + lane;
    const float* cp = cand + lane;
    float* hp = h_all + BD + lane;
    __half* hip = hhi + lane;
    for (int t = 0; t < T; ++t) {
        float d = dp[(size_t)t * BD], c = cp[(size_t)t * BD];
        float cv = tanhf(fmaf(rh, h, c));
        h = fmaf(d, cv - h, h);
        hp[(size_t)t * BD] = h;
        hip[(size_t)t * BD] = __float2half_rn(h);
    }
}

// ---------------------------------------------------------------------------
extern "C" void kernel_launch(void* const* d_in, const int* in_sizes, int n_in,
                              void* d_out, int out_size)
{
    const float* x       = (const float*)d_in[0];
    const float* h0      = (const float*)d_in[1];
    const float* W_x     = (const float*)d_in[2];
    const float* r_h     = (const float*)d_in[3];
    const float* b       = (const float*)d_in[4];
    const float* W_delta = (const float*)d_in[5];
    const float* b_delta = (const float*)d_in[6];
    const float* W_out   = (const float*)d_in[7];
    float* out = (float*)d_out;

    int D  = (int)(sqrt((double)in_sizes[2]) + 0.5);
    int Bn = in_sizes[1] / D;
    int Tn = in_sizes[0] / (Bn * D);
    int BD = Bn * D;
    int M  = Tn * Bn;
    int DD = D * D;

    float *gd, *gc, *ghall, *gA, *gB, *ghb;
    __half *xh, *hh, *wh, *woh;
    cudaGetSymbolAddress((void**)&gd,    g_delta);
    cudaGetSymbolAddress((void**)&gc,    g_cand);
    cudaGetSymbolAddress((void**)&ghall, g_hall);
    cudaGetSymbolAddress((void**)&xh,    g_xh);
    cudaGetSymbolAddress((void**)&hh,    g_hh);
    cudaGetSymbolAddress((void**)&wh,    g_wh);
    cudaGetSymbolAddress((void**)&woh,   g_woh);
    cudaGetSymbolAddress((void**)&gA,    g_Abuf);
    cudaGetSymbolAddress((void**)&gB,    g_Bbuf);
    cudaGetSymbolAddress((void**)&ghb,   g_hb);

    float *hall, *outs;
    long need_both = (long)(Tn + 1) * BD + (long)M * D;
    if ((long)out_size >= need_both) {
        hall = out;
        outs = out + (size_t)(Tn + 1) * BD;
    } else {
        hall = ghall;
        outs = out;
    }

    cudaFuncSetAttribute(gemm_f16<0>, cudaFuncAttributeMaxDynamicSharedMemorySize, GSMEM);
    cudaFuncSetAttribute(gemm_f16<1>, cudaFuncAttributeMaxDynamicSharedMemorySize, GSMEM);

    // Phase 0: fp16 conversions + r_h flag
    int n4x = (M * D) / 4;
    int n4w = DD / 4;
    cvt_f16<<<(n4x + 255) / 256, 256>>>(x, xh, n4x);
    cvt_f16<<<(n4w + 255) / 256, 256>>>(W_delta, wh,      n4w);
    cvt_f16<<<(n4w + 255) / 256, 256>>>(W_x,     wh + DD, n4w);
    cvt_f16<<<(n4w + 255) / 256, 256>>>(W_out,   woh,     n4w);
    rh_flag_kernel<<<1, 256>>>(r_h, D);

    // Phase 1: fused delta|cand GEMM (N = 2D, split at D)
    gemm_f16<0><<<dim3(2 * D / 128, M / 128), 256, GSMEM>>>(
        xh, wh, b_delta, b, gd, gc, nullptr, D, D, D);

    // Phase 2: scan — parallel chunked fast path (r_h==0) + sequential fallback
    {
        int CHK = 128;
        while (Tn % CHK) CHK >>= 1;                 // Tn is a power-of-2 multiple
        int NCHK = Tn / CHK;
        if (NCHK > MAX_NCHK) { CHK = Tn / MAX_NCHK; NCHK = MAX_NCHK; }
        dim3 gch(BD / 256, NCHK);
        scan_part1<<<gch, 256>>>(gd, gc, gA, gB, BD, CHK);
        scan_part2<<<BD / 256, 256>>>(gA, gB, h0, ghb, hall, BD, NCHK);
        scan_part3<<<gch, 256>>>(gd, gc, ghb, hall, hh, BD, CHK);
        scan_seq<<<(BD + 127) / 128, 128>>>(gd, gc, h0, r_h, hall, hh, Tn, BD, D);
    }

    // Phase 3: output GEMM with fused compete-softmax + silu epilogue
    gemm_f16<1><<<dim3(D / 128, M / 128), 256, GSMEM>>>(
        hh, woh, nullptr, nullptr, outs, nullptr, hall + BD, D, D, 0);
}

// round 9
// speedup vs baseline: 5.3237x; 1.0366x over previous
#include <cuda_runtime.h>
#include <cuda_fp16.h>
#include <math.h>
#include <stdint.h>

// ---------------------------------------------------------------------------
// Scratch (no allocation allowed)
// ---------------------------------------------------------------------------
#define MAX_TBD (2048*16*1024)
#define MAX_HALL ((2048+1)*16*1024)
#define MAX_BD   (16*1024)
#define MAX_NCHK 64
__device__ __half g_dh[MAX_TBD];        // delta fp16 (GEMM0 out)
__device__ __half g_ch[MAX_TBD];        // cand  fp16 (GEMM0 out)
__device__ float g_hall[MAX_HALL];      // fallback if d_out holds only outs
__device__ __half g_xh[MAX_TBD];        // x fp16
__device__ __half g_hh[MAX_TBD];        // h fp16 (written by scan)
__device__ __half g_wh[2*1024*1024];    // [W_delta ; W_x] fp16
__device__ __half g_woh[1024*1024];     // W_out fp16
__device__ float g_Abuf[MAX_NCHK*MAX_BD];
__device__ float g_Bbuf[MAX_NCHK*MAX_BD];
__device__ float g_hb[MAX_NCHK*MAX_BD];
__device__ int   g_rh_zero;

// ---------------------------------------------------------------------------
// Helpers
// ---------------------------------------------------------------------------
__device__ __forceinline__ uint32_t smem_u32(const void* p) {
    uint32_t a;
    asm("{ .reg .u64 t; cvta.to.shared.u64 t, %1; cvt.u32.u64 %0, t; }" : "=r"(a) : "l"(p));
    return a;
}

#define LDSM_X4(r0, r1, r2, r3, addr) \
    asm volatile("ldmatrix.sync.aligned.m8n8.x4.shared.b16 {%0,%1,%2,%3}, [%4];" \
                 : "=r"(r0), "=r"(r1), "=r"(r2), "=r"(r3) : "r"(addr))

#define MMAF16(c, a, b0, b1) \
    asm volatile("mma.sync.aligned.m16n8k16.row.col.f32.f16.f16.f32 " \
                 "{%0,%1,%2,%3},{%4,%5,%6,%7},{%8,%9},{%0,%1,%2,%3};" \
                 : "+f"((c)[0]), "+f"((c)[1]), "+f"((c)[2]), "+f"((c)[3]) \
                 : "r"((a)[0]), "r"((a)[1]), "r"((a)[2]), "r"((a)[3]), \
                   "r"(b0), "r"(b1))

#define CP16(dst, src) \
    asm volatile("cp.async.cg.shared.global [%0], [%1], 16;" :: "r"(dst), "l"(src) : "memory")
#define CP_COMMIT() asm volatile("cp.async.commit_group;" ::: "memory")
#define CP_WAIT1()  asm volatile("cp.async.wait_group 1;" ::: "memory")
#define CP_WAIT0()  asm volatile("cp.async.wait_group 0;" ::: "memory")

// fp32 -> fp16 RN, vectorized x4
__global__ void cvt_f16(const float* __restrict__ src,
                        __half* __restrict__ dst, int n4)
{
    int i = blockIdx.x * blockDim.x + threadIdx.x;
    if (i >= n4) return;
    float4 f = ((const float4*)src)[i];
    ((__half2*)dst)[2*i]   = __halves2half2(__float2half_rn(f.x), __float2half_rn(f.y));
    ((__half2*)dst)[2*i+1] = __halves2half2(__float2half_rn(f.z), __float2half_rn(f.w));
}

// ---------------------------------------------------------------------------
// fp16 1-pass HMMA GEMM: C = epi( A[M,K] @ B[N,K]^T ), fp32 accum.
// CTA 128x128, 8 warps (2x4), warp tile 64x32, BK=32, cp.async 3-stage ring,
// one __syncthreads per chunk. Padded smem rows: 32 fp16 + 16B pad = 80B.
// MODE 0: n0 <  nSplit -> fp16( sigmoid(acc+bias0) ) -> out0 (delta, fp16)
//         n0 >= nSplit -> fp16(        acc+bias1   ) -> out1 (cand,  fp16)
// MODE 1: compete(hsrc fp16) * silu(acc) -> out0 (fp32)
// ---------------------------------------------------------------------------
#define STG_B    10240
#define STAGE_SZ 20480
#define NSTAGE   3
#define GSMEM (NSTAGE * STAGE_SZ)

template <int MODE>
__global__ void __launch_bounds__(256, 2) gemm_f16(
    const __half* __restrict__ Ah,
    const __half* __restrict__ Bh,
    const float* __restrict__ bias0,
    const float* __restrict__ bias1,
    void* __restrict__ out0v,
    void* __restrict__ out1v,
    const __half* __restrict__ hsrc,
    int K, int ldC, int nSplit)
{
    extern __shared__ __align__(1024) char smem[];
    const uint32_t sb = smem_u32(smem);
    const int tid = threadIdx.x, wid = tid >> 5, lid = tid & 31;
    const int m0 = blockIdx.y * 128;
    const int n0 = blockIdx.x * 128;

    const size_t aOff = (size_t)(m0 + (tid >> 1)) * K + (size_t)(tid & 1) * 16;
    const size_t bOff = (size_t)(n0 + (tid >> 1)) * K + (size_t)(tid & 1) * 16;
    const uint32_t dOff = (uint32_t)(tid >> 1) * 80 + (uint32_t)(tid & 1) * 32;

    const int wm = wid >> 2, wn = wid & 3;
    const uint32_t aoff = ((uint32_t)((lid & 7) + ((lid >> 3) & 1) * 8) + (uint32_t)wm * 64) * 80
                        + (uint32_t)(lid >> 4) * 16;
    const uint32_t boff = ((uint32_t)((lid & 7) + (lid >> 4) * 8) + (uint32_t)wn * 32) * 80
                        + (uint32_t)((lid >> 3) & 1) * 16;

    float acc[4][4][4];
#pragma unroll
    for (int i = 0; i < 4; ++i)
#pragma unroll
        for (int j = 0; j < 4; ++j)
#pragma unroll
            for (int q = 0; q < 4; ++q) acc[i][j][q] = 0.f;

    const int NCH = K / 32;

    auto issue = [&](int ch, int s) {
        const uint32_t stb = sb + (uint32_t)s * STAGE_SZ;
        const size_t ko = (size_t)ch * 32;
        const __half* a1 = Ah + aOff + ko;
        const __half* b1 = Bh + bOff + ko;
        uint32_t d = stb + dOff;
        CP16(d,            a1);  CP16(d + 16,            a1 + 8);
        CP16(d + STG_B,    b1);  CP16(d + STG_B + 16,    b1 + 8);
    };

    issue(0, 0); CP_COMMIT();
    issue(1, 1); CP_COMMIT();

#pragma unroll 1
    for (int ch = 0; ch < NCH; ++ch) {
        const int s = ch % NSTAGE;
        if (ch + 1 < NCH) CP_WAIT1(); else CP_WAIT0();
        __syncthreads();   // stage s ready; stage (ch+2)%3 == (ch-1)%3 drained
        if (ch + 2 < NCH) { issue(ch + 2, (ch + 2) % NSTAGE); CP_COMMIT(); }

        const uint32_t stA = sb + (uint32_t)s * STAGE_SZ;
#pragma unroll
        for (int kk = 0; kk < 2; ++kk) {
            const uint32_t kof = (uint32_t)kk * 32;
            uint32_t bh[4][2];
            LDSM_X4(bh[0][0], bh[0][1], bh[1][0], bh[1][1],
                    stA + STG_B + boff + kof);
            LDSM_X4(bh[2][0], bh[2][1], bh[3][0], bh[3][1],
                    stA + STG_B + boff + 1280 + kof);
            uint32_t ah[4][4];
#pragma unroll
            for (int mi = 0; mi < 4; ++mi)
                LDSM_X4(ah[mi][0], ah[mi][1], ah[mi][2], ah[mi][3],
                        stA + aoff + (uint32_t)mi * 1280 + kof);
#pragma unroll
            for (int mi = 0; mi < 4; ++mi)
#pragma unroll
                for (int nj = 0; nj < 4; ++nj)
                    MMAF16(acc[mi][nj], ah[mi], bh[nj][0], bh[nj][1]);
        }
    }

    // ---- epilogue ----
    const int qr = lid >> 2;       // 0..7
    const int qc = 2 * (lid & 3);  // 0,2,4,6
    const int gcol0 = n0 + wn * 32;

    if (MODE == 0) {
        const int sel = (n0 >= nSplit);
        const float* bias = sel ? bias1 : bias0;
        __half* Cout = sel ? (__half*)out1v : (__half*)out0v;
        const int colBase = gcol0 - sel * nSplit;
        float bv[8];
#pragma unroll
        for (int nj = 0; nj < 4; ++nj) {
            float2 t = *(const float2*)(bias + colBase + nj * 8 + qc);
            bv[2*nj] = t.x; bv[2*nj+1] = t.y;
        }
#pragma unroll
        for (int mi = 0; mi < 4; ++mi) {
            const int r0 = m0 + wm * 64 + mi * 16 + qr;
#pragma unroll
            for (int nj = 0; nj < 4; ++nj) {
                const int c = colBase + nj * 8 + qc;
                float v0 = acc[mi][nj][0] + bv[2*nj];
                float v1 = acc[mi][nj][1] + bv[2*nj+1];
                float v2 = acc[mi][nj][2] + bv[2*nj];
                float v3 = acc[mi][nj][3] + bv[2*nj+1];
                if (!sel) {
                    v0 = 1.f / (1.f + __expf(-v0));
                    v1 = 1.f / (1.f + __expf(-v1));
                    v2 = 1.f / (1.f + __expf(-v2));
                    v3 = 1.f / (1.f + __expf(-v3));
                }
                *(__half2*)(Cout + (size_t)r0 * ldC + c) =
                    __halves2half2(__float2half_rn(v0), __float2half_rn(v1));
                *(__half2*)(Cout + (size_t)(r0 + 8) * ldC + c) =
                    __halves2half2(__float2half_rn(v2), __float2half_rn(v3));
            }
        }
    } else {
        float* Cout = (float*)out0v;
#pragma unroll
        for (int mi = 0; mi < 4; ++mi) {
            const int r0 = m0 + wm * 64 + mi * 16 + qr;
            const int r1 = r0 + 8;
            float h0v[8], h1v[8];
#pragma unroll
            for (int nj = 0; nj < 4; ++nj) {
                const int c = gcol0 + nj * 8 + qc;
                float2 t0 = __half22float2(*(const __half2*)(hsrc + (size_t)r0 * ldC + c));
                float2 t1 = __half22float2(*(const __half2*)(hsrc + (size_t)r1 * ldC + c));
                h0v[2*nj] = t0.x; h0v[2*nj+1] = t0.y;
                h1v[2*nj] = t1.x; h1v[2*nj+1] = t1.y;
            }
            float mx0 = h0v[0], mx1 = h1v[0];
#pragma unroll
            for (int k = 1; k < 8; ++k) {
                mx0 = fmaxf(mx0, h0v[k]);
                mx1 = fmaxf(mx1, h1v[k]);
            }
            mx0 = fmaxf(mx0, __shfl_xor_sync(0xffffffffu, mx0, 1));
            mx0 = fmaxf(mx0, __shfl_xor_sync(0xffffffffu, mx0, 2));
            mx1 = fmaxf(mx1, __shfl_xor_sync(0xffffffffu, mx1, 1));
            mx1 = fmaxf(mx1, __shfl_xor_sync(0xffffffffu, mx1, 2));
            float s0 = 0.f, s1 = 0.f;
#pragma unroll
            for (int k = 0; k < 8; ++k) {
                h0v[k] = __expf(h0v[k] - mx0); s0 += h0v[k];
                h1v[k] = __expf(h1v[k] - mx1); s1 += h1v[k];
            }
            s0 += __shfl_xor_sync(0xffffffffu, s0, 1);
            s0 += __shfl_xor_sync(0xffffffffu, s0, 2);
            s1 += __shfl_xor_sync(0xffffffffu, s1, 1);
            s1 += __shfl_xor_sync(0xffffffffu, s1, 2);
            const float inv0 = 1.f / s0, inv1 = 1.f / s1;
#pragma unroll
            for (int nj = 0; nj < 4; ++nj) {
                const int c = gcol0 + nj * 8 + qc;
                float y0 = acc[mi][nj][0], y1 = acc[mi][nj][1];
                float y2 = acc[mi][nj][2], y3 = acc[mi][nj][3];
                float v0 = (h0v[2*nj]   * inv0) * (y0 / (1.f + __expf(-y0)));
                float v1 = (h0v[2*nj+1] * inv0) * (y1 / (1.f + __expf(-y1)));
                float v2 = (h1v[2*nj]   * inv1) * (y2 / (1.f + __expf(-y2)));
                float v3 = (h1v[2*nj+1] * inv1) * (y3 / (1.f + __expf(-y3)));
                *(float2*)(Cout + (size_t)r0 * ldC + c) = make_float2(v0, v1);
                *(float2*)(Cout + (size_t)r1 * ldC + c) = make_float2(v2, v3);
            }
        }
    }
}

// ---------------------------------------------------------------------------
// Scan: parallel fast path when r_h == 0 (linear recurrence), else sequential.
// delta/cand are fp16; each fast-path thread handles 2 lanes via __half2.
// ---------------------------------------------------------------------------
__global__ void rh_flag_kernel(const float* __restrict__ r_h, int D)
{
    int nz = 0;
    for (int i = threadIdx.x; i < D; i += blockDim.x)
        if (r_h[i] != 0.f) nz = 1;
    if (__syncthreads_or(nz)) { if (threadIdx.x == 0) g_rh_zero = 0; }
    else                      { if (threadIdx.x == 0) g_rh_zero = 1; }
}

// Phase 1: per-chunk affine composition (A,B): h_end = A*h_start + B
__global__ void scan_part1(const __half* __restrict__ delta,
                           const __half* __restrict__ cand,
                           float* __restrict__ Abuf,
                           float* __restrict__ Bbuf,
                           int BD, int CHK)
{
    if (!g_rh_zero) return;
    const int l2 = blockIdx.x * blockDim.x + threadIdx.x;   // pair index
    const int cc = blockIdx.y;
    const int BD2 = BD >> 1;
    const __half2* dp = (const __half2*)delta + (size_t)cc * CHK * BD2 + l2;
    const __half2* cp = (const __half2*)cand  + (size_t)cc * CHK * BD2 + l2;
    float Ax = 1.f, Ay = 1.f, Bx = 0.f, By = 0.f;
#pragma unroll 4
    for (int u = 0; u < CHK; ++u) {
        float2 d = __half22float2(dp[(size_t)u * BD2]);
        float2 c = __half22float2(cp[(size_t)u * BD2]);
        float ax = 1.f - d.x, ay = 1.f - d.y;
        float bx = d.x * tanhf(c.x), by = d.y * tanhf(c.y);
        Ax *= ax; Ay *= ay;
        Bx = fmaf(ax, Bx, bx); By = fmaf(ay, By, by);
    }
    *(float2*)(Abuf + (size_t)cc * BD + 2 * l2) = make_float2(Ax, Ay);
    *(float2*)(Bbuf + (size_t)cc * BD + 2 * l2) = make_float2(Bx, By);
}

// Phase 2: boundary scan across chunks (NCHK steps)
__global__ void scan_part2(const float* __restrict__ Abuf,
                           const float* __restrict__ Bbuf,
                           const float* __restrict__ h0,
                           float* __restrict__ hb,
                           float* __restrict__ h_all,
                           int BD, int NCHK)
{
    if (!g_rh_zero) return;
    const int lane = blockIdx.x * blockDim.x + threadIdx.x;
    float h = h0[lane];
    h_all[lane] = h;
#pragma unroll 4
    for (int cc = 0; cc < NCHK; ++cc) {
        hb[(size_t)cc * BD + lane] = h;
        h = fmaf(Abuf[(size_t)cc * BD + lane], h, Bbuf[(size_t)cc * BD + lane]);
    }
}

// Phase 3: recompute within chunk from boundary, write h_all fp32 + h fp16
__global__ void scan_part3(const __half* __restrict__ delta,
                           const __half* __restrict__ cand,
                           const float* __restrict__ hb,
                           float* __restrict__ h_all,
                           __half* __restrict__ hhi,
                           int BD, int CHK)
{
    if (!g_rh_zero) return;
    const int l2 = blockIdx.x * blockDim.x + threadIdx.x;
    const int cc = blockIdx.y;
    const int BD2 = BD >> 1;
    const __half2* dp = (const __half2*)delta + (size_t)cc * CHK * BD2 + l2;
    const __half2* cp = (const __half2*)cand  + (size_t)cc * CHK * BD2 + l2;
    __half2* hp16 = (__half2*)hhi + (size_t)cc * CHK * BD2 + l2;
    float2* hp32 = (float2*)(h_all + BD) + (size_t)cc * CHK * BD2 + l2;
    float2 h = *(const float2*)(hb + (size_t)cc * BD + 2 * l2);
#pragma unroll 4
    for (int u = 0; u < CHK; ++u) {
        float2 d = __half22float2(dp[(size_t)u * BD2]);
        float2 c = __half22float2(cp[(size_t)u * BD2]);
        h.x = fmaf(d.x, tanhf(c.x) - h.x, h.x);
        h.y = fmaf(d.y, tanhf(c.y) - h.y, h.y);
        hp32[(size_t)u * BD2] = h;
        hp16[(size_t)u * BD2] = __halves2half2(__float2half_rn(h.x), __float2half_rn(h.y));
    }
}

// Fallback: sequential scan (general r_h) — runs only when g_rh_zero == 0
__global__ void scan_seq(const __half* __restrict__ delta,
                         const __half* __restrict__ cand,
                         const float* __restrict__ h0,
                         const float* __restrict__ r_h,
                         float* __restrict__ h_all,
                         __half* __restrict__ hhi,
                         int T, int BD, int D)
{
    if (g_rh_zero) return;
    int lane = blockIdx.x * blockDim.x + threadIdx.x;
    if (lane >= BD) return;
    float h = h0[lane];
    float rh = r_h[lane % D];
    h_all[lane] = h;
    for (int t = 0; t < T; ++t) {
        float d = __half2float(delta[(size_t)t * BD + lane]);
        float c = __half2float(cand[(size_t)t * BD + lane]);
        float cv = tanhf(fmaf(rh, h, c));
        h = fmaf(d, cv - h, h);
        h_all[BD + (size_t)t * BD + lane] = h;
        hhi[(size_t)t * BD + lane] = __float2half_rn(h);
    }
}

// ---------------------------------------------------------------------------
extern "C" void kernel_launch(void* const* d_in, const int* in_sizes, int n_in,
                              void* d_out, int out_size)
{
    const float* x       = (const float*)d_in[0];
    const float* h0      = (const float*)d_in[1];
    const float* W_x     = (const float*)d_in[2];
    const float* r_h     = (const float*)d_in[3];
    const float* b       = (const float*)d_in[4];
    const float* W_delta = (const float*)d_in[5];
    const float* b_delta = (const float*)d_in[6];
    const float* W_out   = (const float*)d_in[7];
    float* out = (float*)d_out;

    int D  = (int)(sqrt((double)in_sizes[2]) + 0.5);
    int Bn = in_sizes[1] / D;
    int Tn = in_sizes[0] / (Bn * D);
    int BD = Bn * D;
    int M  = Tn * Bn;
    int DD = D * D;

    float *ghall, *gA, *gB, *ghb;
    __half *gdh, *gch, *xh, *hh, *wh, *woh;
    cudaGetSymbolAddress((void**)&gdh,   g_dh);
    cudaGetSymbolAddress((void**)&gch,   g_ch);
    cudaGetSymbolAddress((void**)&ghall, g_hall);
    cudaGetSymbolAddress((void**)&xh,    g_xh);
    cudaGetSymbolAddress((void**)&hh,    g_hh);
    cudaGetSymbolAddress((void**)&wh,    g_wh);
    cudaGetSymbolAddress((void**)&woh,   g_woh);
    cudaGetSymbolAddress((void**)&gA,    g_Abuf);
    cudaGetSymbolAddress((void**)&gB,    g_Bbuf);
    cudaGetSymbolAddress((void**)&ghb,   g_hb);

    float *hall, *outs;
    long need_both = (long)(Tn + 1) * BD + (long)M * D;
    if ((long)out_size >= need_both) {
        hall = out;
        outs = out + (size_t)(Tn + 1) * BD;
    } else {
        hall = ghall;
        outs = out;
    }

    cudaFuncSetAttribute(gemm_f16<0>, cudaFuncAttributeMaxDynamicSharedMemorySize, GSMEM);
    cudaFuncSetAttribute(gemm_f16<1>, cudaFuncAttributeMaxDynamicSharedMemorySize, GSMEM);

    // Phase 0: fp16 conversions + r_h flag
    int n4x = (M * D) / 4;
    int n4w = DD / 4;
    rh_flag_kernel<<<1, 256>>>(r_h, D);
    cvt_f16<<<(n4x + 255) / 256, 256>>>(x, xh, n4x);
    cvt_f16<<<(n4w + 255) / 256, 256>>>(W_delta, wh,      n4w);
    cvt_f16<<<(n4w + 255) / 256, 256>>>(W_x,     wh + DD, n4w);
    cvt_f16<<<(n4w + 255) / 256, 256>>>(W_out,   woh,     n4w);

    // Phase 1: fused delta|cand GEMM (N = 2D, split at D), fp16 outputs
    gemm_f16<0><<<dim3(2 * D / 128, M / 128), 256, GSMEM>>>(
        xh, wh, b_delta, b, gdh, gch, nullptr, D, D, D);

    // Phase 2: scan — parallel chunked fast path (r_h==0) + sequential fallback
    {
        int CHK = 128;
        while (Tn % CHK) CHK >>= 1;
        int NCHK = Tn / CHK;
        if (NCHK > MAX_NCHK) { CHK = Tn / MAX_NCHK; NCHK = MAX_NCHK; }
        dim3 gch2(BD / 512, NCHK);          // 2 lanes per thread
        scan_part1<<<gch2, 256>>>(gdh, gch, gA, gB, BD, CHK);
        scan_part2<<<BD / 256, 256>>>(gA, gB, h0, ghb, hall, BD, NCHK);
        scan_part3<<<gch2, 256>>>(gdh, gch, ghb, hall, hh, BD, CHK);
        scan_seq<<<(BD + 127) / 128, 128>>>(gdh, gch, h0, r_h, hall, hh, Tn, BD, D);
    }

    // Phase 3: output GEMM with fused compete-softmax + silu epilogue
    gemm_f16<1><<<dim3(D / 128, M / 128), 256, GSMEM>>>(
        hh, woh, nullptr, nullptr, outs, nullptr, hh, D, D, 0);
}

// round 10
// speedup vs baseline: 5.3913x; 1.0127x over previous
#include <cuda_runtime.h>
#include <cuda_fp16.h>
#include <math.h>
#include <stdint.h>

// ---------------------------------------------------------------------------
// Scratch (no allocation allowed)
// ---------------------------------------------------------------------------
#define MAX_TBD (2048*16*1024)
#define MAX_HALL ((2048+1)*16*1024)
#define MAX_BD   (16*1024)
#define MAX_NCHK 64
__device__ __half g_dh[MAX_TBD];        // delta fp16 (GEMM0 out)
__device__ __half g_ch[MAX_TBD];        // cand  fp16 (GEMM0 out)
__device__ float g_hall[MAX_HALL];      // fallback if d_out holds only outs
__device__ __half g_xh[MAX_TBD];        // x fp16
__device__ __half g_hh[MAX_TBD];        // h fp16 (written by scan)
__device__ __half g_wh[2*1024*1024];    // [W_delta ; W_x] fp16
__device__ __half g_woh[1024*1024];     // W_out fp16
__device__ float g_Abuf[MAX_NCHK*MAX_BD];
__device__ float g_Bbuf[MAX_NCHK*MAX_BD];
__device__ float g_hb[MAX_NCHK*MAX_BD];
__device__ int   g_rh_zero;

// ---------------------------------------------------------------------------
// Helpers
// ---------------------------------------------------------------------------
__device__ __forceinline__ uint32_t smem_u32(const void* p) {
    uint32_t a;
    asm("{ .reg .u64 t; cvta.to.shared.u64 t, %1; cvt.u32.u64 %0, t; }" : "=r"(a) : "l"(p));
    return a;
}

#define LDSM_X4(r0, r1, r2, r3, addr) \
    asm volatile("ldmatrix.sync.aligned.m8n8.x4.shared.b16 {%0,%1,%2,%3}, [%4];" \
                 : "=r"(r0), "=r"(r1), "=r"(r2), "=r"(r3) : "r"(addr))

#define MMAF16(c, a, b0, b1) \
    asm volatile("mma.sync.aligned.m16n8k16.row.col.f32.f16.f16.f32 " \
                 "{%0,%1,%2,%3},{%4,%5,%6,%7},{%8,%9},{%0,%1,%2,%3};" \
                 : "+f"((c)[0]), "+f"((c)[1]), "+f"((c)[2]), "+f"((c)[3]) \
                 : "r"((a)[0]), "r"((a)[1]), "r"((a)[2]), "r"((a)[3]), \
                   "r"(b0), "r"(b1))

#define CP16(dst, src) \
    asm volatile("cp.async.cg.shared.global [%0], [%1], 16;" :: "r"(dst), "l"(src) : "memory")
#define CP_COMMIT() asm volatile("cp.async.commit_group;" ::: "memory")
#define CP_WAIT2()  asm volatile("cp.async.wait_group 2;" ::: "memory")
#define CP_WAIT1()  asm volatile("cp.async.wait_group 1;" ::: "memory")
#define CP_WAIT0()  asm volatile("cp.async.wait_group 0;" ::: "memory")

// ---------------------------------------------------------------------------
// One fused fp32 -> fp16 conversion for x + the three weights
// layout: [0, n4x) -> x->xh ; then 3 blocks of n4w -> W_delta, W_x, W_out
// ---------------------------------------------------------------------------
__global__ void cvt_all(const float* __restrict__ x,
                        const float* __restrict__ wd,
                        const float* __restrict__ wx,
                        const float* __restrict__ wo,
                        __half* __restrict__ xh,
                        __half* __restrict__ wh,
                        __half* __restrict__ woh,
                        int n4x, int n4w)
{
    int i = blockIdx.x * blockDim.x + threadIdx.x;
    const float* src;
    __half* dst;
    int off;
    if (i < n4x) {
        src = x; dst = xh; off = i;
    } else {
        int w = i - n4x;
        int which = w / n4w;
        if (which >= 3) return;
        off = w - which * n4w;
        if (which == 0)      { src = wd; dst = wh; }
        else if (which == 1) { src = wx; dst = wh + (size_t)n4w * 4; }
        else                 { src = wo; dst = woh; }
    }
    float4 f = ((const float4*)src)[off];
    ((__half2*)dst)[2*off]   = __halves2half2(__float2half_rn(f.x), __float2half_rn(f.y));
    ((__half2*)dst)[2*off+1] = __halves2half2(__float2half_rn(f.z), __float2half_rn(f.w));
}

// ---------------------------------------------------------------------------
// fp16 1-pass HMMA GEMM: C = epi( A[M,K] @ B[N,K]^T ), fp32 accum.
// CTA 128x128, 8 warps (2x4), warp tile 64x32, BK=32, cp.async 4-stage ring,
// one __syncthreads per chunk. Padded smem rows: 32 fp16 + 16B pad = 80B.
// MODE 0: n0 <  nSplit -> fp16( sigmoid(acc+bias0) ) -> out0 (delta, fp16)
//         n0 >= nSplit -> fp16(        acc+bias1   ) -> out1 (cand,  fp16)
// MODE 1: compete(hsrc fp16) * silu(acc) -> out0 (fp32, streaming store)
// ---------------------------------------------------------------------------
#define STG_B    10240
#define STAGE_SZ 20480
#define NSTAGE   4
#define GSMEM (NSTAGE * STAGE_SZ)

template <int MODE>
__global__ void __launch_bounds__(256, 2) gemm_f16(
    const __half* __restrict__ Ah,
    const __half* __restrict__ Bh,
    const float* __restrict__ bias0,
    const float* __restrict__ bias1,
    void* __restrict__ out0v,
    void* __restrict__ out1v,
    const __half* __restrict__ hsrc,
    int K, int ldC, int nSplit)
{
    extern __shared__ __align__(1024) char smem[];
    const uint32_t sb = smem_u32(smem);
    const int tid = threadIdx.x, wid = tid >> 5, lid = tid & 31;
    const int m0 = blockIdx.y * 128;
    const int n0 = blockIdx.x * 128;

    const size_t aOff = (size_t)(m0 + (tid >> 1)) * K + (size_t)(tid & 1) * 16;
    const size_t bOff = (size_t)(n0 + (tid >> 1)) * K + (size_t)(tid & 1) * 16;
    const uint32_t dOff = (uint32_t)(tid >> 1) * 80 + (uint32_t)(tid & 1) * 32;

    const int wm = wid >> 2, wn = wid & 3;
    const uint32_t aoff = ((uint32_t)((lid & 7) + ((lid >> 3) & 1) * 8) + (uint32_t)wm * 64) * 80
                        + (uint32_t)(lid >> 4) * 16;
    const uint32_t boff = ((uint32_t)((lid & 7) + (lid >> 4) * 8) + (uint32_t)wn * 32) * 80
                        + (uint32_t)((lid >> 3) & 1) * 16;

    float acc[4][4][4];
#pragma unroll
    for (int i = 0; i < 4; ++i)
#pragma unroll
        for (int j = 0; j < 4; ++j)
#pragma unroll
            for (int q = 0; q < 4; ++q) acc[i][j][q] = 0.f;

    const int NCH = K / 32;

    auto issue = [&](int ch, int s) {
        const uint32_t stb = sb + (uint32_t)s * STAGE_SZ;
        const size_t ko = (size_t)ch * 32;
        const __half* a1 = Ah + aOff + ko;
        const __half* b1 = Bh + bOff + ko;
        uint32_t d = stb + dOff;
        CP16(d,            a1);  CP16(d + 16,            a1 + 8);
        CP16(d + STG_B,    b1);  CP16(d + STG_B + 16,    b1 + 8);
    };

    issue(0, 0); CP_COMMIT();
    issue(1, 1); CP_COMMIT();
    issue(2, 2); CP_COMMIT();

#pragma unroll 1
    for (int ch = 0; ch < NCH; ++ch) {
        const int s = ch & (NSTAGE - 1);
        if (ch + 2 < NCH)      CP_WAIT2();
        else if (ch + 1 < NCH) CP_WAIT1();
        else                   CP_WAIT0();
        __syncthreads();   // stage s ready; refill target (ch+3)%4==(ch-1)%4 drained
        if (ch + 3 < NCH) { issue(ch + 3, (ch + 3) & (NSTAGE - 1)); CP_COMMIT(); }

        const uint32_t stA = sb + (uint32_t)s * STAGE_SZ;
#pragma unroll
        for (int kk = 0; kk < 2; ++kk) {
            const uint32_t kof = (uint32_t)kk * 32;
            uint32_t bh[4][2];
            LDSM_X4(bh[0][0], bh[0][1], bh[1][0], bh[1][1],
                    stA + STG_B + boff + kof);
            LDSM_X4(bh[2][0], bh[2][1], bh[3][0], bh[3][1],
                    stA + STG_B + boff + 1280 + kof);
            uint32_t ah[4][4];
#pragma unroll
            for (int mi = 0; mi < 4; ++mi)
                LDSM_X4(ah[mi][0], ah[mi][1], ah[mi][2], ah[mi][3],
                        stA + aoff + (uint32_t)mi * 1280 + kof);
#pragma unroll
            for (int mi = 0; mi < 4; ++mi)
#pragma unroll
                for (int nj = 0; nj < 4; ++nj)
                    MMAF16(acc[mi][nj], ah[mi], bh[nj][0], bh[nj][1]);
        }
    }

    // ---- epilogue ----
    const int qr = lid >> 2;       // 0..7
    const int qc = 2 * (lid & 3);  // 0,2,4,6
    const int gcol0 = n0 + wn * 32;

    if (MODE == 0) {
        const int sel = (n0 >= nSplit);
        const float* bias = sel ? bias1 : bias0;
        __half* Cout = sel ? (__half*)out1v : (__half*)out0v;
        const int colBase = gcol0 - sel * nSplit;
        float bv[8];
#pragma unroll
        for (int nj = 0; nj < 4; ++nj) {
            float2 t = *(const float2*)(bias + colBase + nj * 8 + qc);
            bv[2*nj] = t.x; bv[2*nj+1] = t.y;
        }
#pragma unroll
        for (int mi = 0; mi < 4; ++mi) {
            const int r0 = m0 + wm * 64 + mi * 16 + qr;
#pragma unroll
            for (int nj = 0; nj < 4; ++nj) {
                const int c = colBase + nj * 8 + qc;
                float v0 = acc[mi][nj][0] + bv[2*nj];
                float v1 = acc[mi][nj][1] + bv[2*nj+1];
                float v2 = acc[mi][nj][2] + bv[2*nj];
                float v3 = acc[mi][nj][3] + bv[2*nj+1];
                if (!sel) {
                    v0 = 1.f / (1.f + __expf(-v0));
                    v1 = 1.f / (1.f + __expf(-v1));
                    v2 = 1.f / (1.f + __expf(-v2));
                    v3 = 1.f / (1.f + __expf(-v3));
                }
                *(__half2*)(Cout + (size_t)r0 * ldC + c) =
                    __halves2half2(__float2half_rn(v0), __float2half_rn(v1));
                *(__half2*)(Cout + (size_t)(r0 + 8) * ldC + c) =
                    __halves2half2(__float2half_rn(v2), __float2half_rn(v3));
            }
        }
    } else {
        float* Cout = (float*)out0v;
#pragma unroll
        for (int mi = 0; mi < 4; ++mi) {
            const int r0 = m0 + wm * 64 + mi * 16 + qr;
            const int r1 = r0 + 8;
            float h0v[8], h1v[8];
#pragma unroll
            for (int nj = 0; nj < 4; ++nj) {
                const int c = gcol0 + nj * 8 + qc;
                float2 t0 = __half22float2(*(const __half2*)(hsrc + (size_t)r0 * ldC + c));
                float2 t1 = __half22float2(*(const __half2*)(hsrc + (size_t)r1 * ldC + c));
                h0v[2*nj] = t0.x; h0v[2*nj+1] = t0.y;
                h1v[2*nj] = t1.x; h1v[2*nj+1] = t1.y;
            }
            float mx0 = h0v[0], mx1 = h1v[0];
#pragma unroll
            for (int k = 1; k < 8; ++k) {
                mx0 = fmaxf(mx0, h0v[k]);
                mx1 = fmaxf(mx1, h1v[k]);
            }
            mx0 = fmaxf(mx0, __shfl_xor_sync(0xffffffffu, mx0, 1));
            mx0 = fmaxf(mx0, __shfl_xor_sync(0xffffffffu, mx0, 2));
            mx1 = fmaxf(mx1, __shfl_xor_sync(0xffffffffu, mx1, 1));
            mx1 = fmaxf(mx1, __shfl_xor_sync(0xffffffffu, mx1, 2));
            float s0 = 0.f, s1 = 0.f;
#pragma unroll
            for (int k = 0; k < 8; ++k) {
                h0v[k] = __expf(h0v[k] - mx0); s0 += h0v[k];
                h1v[k] = __expf(h1v[k] - mx1); s1 += h1v[k];
            }
            s0 += __shfl_xor_sync(0xffffffffu, s0, 1);
            s0 += __shfl_xor_sync(0xffffffffu, s0, 2);
            s1 += __shfl_xor_sync(0xffffffffu, s1, 1);
            s1 += __shfl_xor_sync(0xffffffffu, s1, 2);
            const float inv0 = 1.f / s0, inv1 = 1.f / s1;
#pragma unroll
            for (int nj = 0; nj < 4; ++nj) {
                const int c = gcol0 + nj * 8 + qc;
                float y0 = acc[mi][nj][0], y1 = acc[mi][nj][1];
                float y2 = acc[mi][nj][2], y3 = acc[mi][nj][3];
                float v0 = (h0v[2*nj]   * inv0) * (y0 / (1.f + __expf(-y0)));
                float v1 = (h0v[2*nj+1] * inv0) * (y1 / (1.f + __expf(-y1)));
                float v2 = (h1v[2*nj]   * inv1) * (y2 / (1.f + __expf(-y2)));
                float v3 = (h1v[2*nj+1] * inv1) * (y3 / (1.f + __expf(-y3)));
                __stcs((float2*)(Cout + (size_t)r0 * ldC + c), make_float2(v0, v1));
                __stcs((float2*)(Cout + (size_t)r1 * ldC + c), make_float2(v2, v3));
            }
        }
    }
}

// ---------------------------------------------------------------------------
// Scan: parallel fast path when r_h == 0 (linear recurrence), else sequential.
// ---------------------------------------------------------------------------
__global__ void rh_flag_kernel(const float* __restrict__ r_h, int D)
{
    int nz = 0;
    for (int i = threadIdx.x; i < D; i += blockDim.x)
        if (r_h[i] != 0.f) nz = 1;
    if (__syncthreads_or(nz)) { if (threadIdx.x == 0) g_rh_zero = 0; }
    else                      { if (threadIdx.x == 0) g_rh_zero = 1; }
}

// Phase 1: per-chunk affine composition (A,B): h_end = A*h_start + B
__global__ void scan_part1(const __half* __restrict__ delta,
                           const __half* __restrict__ cand,
                           float* __restrict__ Abuf,
                           float* __restrict__ Bbuf,
                           int BD, int CHK)
{
    if (!g_rh_zero) return;
    const int l2 = blockIdx.x * blockDim.x + threadIdx.x;
    const int cc = blockIdx.y;
    const int BD2 = BD >> 1;
    const __half2* dp = (const __half2*)delta + (size_t)cc * CHK * BD2 + l2;
    const __half2* cp = (const __half2*)cand  + (size_t)cc * CHK * BD2 + l2;
    float Ax = 1.f, Ay = 1.f, Bx = 0.f, By = 0.f;
#pragma unroll 4
    for (int u = 0; u < CHK; ++u) {
        float2 d = __half22float2(dp[(size_t)u * BD2]);
        float2 c = __half22float2(cp[(size_t)u * BD2]);
        float ax = 1.f - d.x, ay = 1.f - d.y;
        float bx = d.x * tanhf(c.x), by = d.y * tanhf(c.y);
        Ax *= ax; Ay *= ay;
        Bx = fmaf(ax, Bx, bx); By = fmaf(ay, By, by);
    }
    *(float2*)(Abuf + (size_t)cc * BD + 2 * l2) = make_float2(Ax, Ay);
    *(float2*)(Bbuf + (size_t)cc * BD + 2 * l2) = make_float2(Bx, By);
}

// Phase 2: boundary scan across chunks (NCHK steps)
__global__ void scan_part2(const float* __restrict__ Abuf,
                           const float* __restrict__ Bbuf,
                           const float* __restrict__ h0,
                           float* __restrict__ hb,
                           float* __restrict__ h_all,
                           int BD, int NCHK)
{
    if (!g_rh_zero) return;
    const int lane = blockIdx.x * blockDim.x + threadIdx.x;
    float h = h0[lane];
    h_all[lane] = h;
#pragma unroll 4
    for (int cc = 0; cc < NCHK; ++cc) {
        hb[(size_t)cc * BD + lane] = h;
        h = fmaf(Abuf[(size_t)cc * BD + lane], h, Bbuf[(size_t)cc * BD + lane]);
    }
}

// Phase 3: recompute within chunk from boundary, write h_all fp32 + h fp16
__global__ void scan_part3(const __half* __restrict__ delta,
                           const __half* __restrict__ cand,
                           const float* __restrict__ hb,
                           float* __restrict__ h_all,
                           __half* __restrict__ hhi,
                           int BD, int CHK)
{
    if (!g_rh_zero) return;
    const int l2 = blockIdx.x * blockDim.x + threadIdx.x;
    const int cc = blockIdx.y;
    const int BD2 = BD >> 1;
    const __half2* dp = (const __half2*)delta + (size_t)cc * CHK * BD2 + l2;
    const __half2* cp = (const __half2*)cand  + (size_t)cc * CHK * BD2 + l2;
    __half2* hp16 = (__half2*)hhi + (size_t)cc * CHK * BD2 + l2;
    float2* hp32 = (float2*)(h_all + BD) + (size_t)cc * CHK * BD2 + l2;
    float2 h = *(const float2*)(hb + (size_t)cc * BD + 2 * l2);
#pragma unroll 4
    for (int u = 0; u < CHK; ++u) {
        float2 d = __half22float2(dp[(size_t)u * BD2]);
        float2 c = __half22float2(cp[(size_t)u * BD2]);
        h.x = fmaf(d.x, tanhf(c.x) - h.x, h.x);
        h.y = fmaf(d.y, tanhf(c.y) - h.y, h.y);
        __stcs(hp32 + (size_t)u * BD2, h);
        hp16[(size_t)u * BD2] = __halves2half2(__float2half_rn(h.x), __float2half_rn(h.y));
    }
}

// Fallback: sequential scan (general r_h) — runs only when g_rh_zero == 0
__global__ void scan_seq(const __half* __restrict__ delta,
                         const __half* __restrict__ cand,
                         const float* __restrict__ h0,
                         const float* __restrict__ r_h,
                         float* __restrict__ h_all,
                         __half* __restrict__ hhi,
                         int T, int BD, int D)
{
    if (g_rh_zero) return;
    int lane = blockIdx.x * blockDim.x + threadIdx.x;
    if (lane >= BD) return;
    float h = h0[lane];
    float rh = r_h[lane % D];
    h_all[lane] = h;
    for (int t = 0; t < T; ++t) {
        float d = __half2float(delta[(size_t)t * BD + lane]);
        float c = __half2float(cand[(size_t)t * BD + lane]);
        float cv = tanhf(fmaf(rh, h, c));
        h = fmaf(d, cv - h, h);
        h_all[BD + (size_t)t * BD + lane] = h;
        hhi[(size_t)t * BD + lane] = __float2half_rn(h);
    }
}

// ---------------------------------------------------------------------------
extern "C" void kernel_launch(void* const* d_in, const int* in_sizes, int n_in,
                              void* d_out, int out_size)
{
    const float* x       = (const float*)d_in[0];
    const float* h0      = (const float*)d_in[1];
    const float* W_x     = (const float*)d_in[2];
    const float* r_h     = (const float*)d_in[3];
    const float* b       = (const float*)d_in[4];
    const float* W_delta = (const float*)d_in[5];
    const float* b_delta = (const float*)d_in[6];
    const float* W_out   = (const float*)d_in[7];
    float* out = (float*)d_out;

    int D  = (int)(sqrt((double)in_sizes[2]) + 0.5);
    int Bn = in_sizes[1] / D;
    int Tn = in_sizes[0] / (Bn * D);
    int BD = Bn * D;
    int M  = Tn * Bn;
    int DD = D * D;

    float *ghall, *gA, *gB, *ghb;
    __half *gdh, *gch, *xh, *hh, *wh, *woh;
    cudaGetSymbolAddress((void**)&gdh,   g_dh);
    cudaGetSymbolAddress((void**)&gch,   g_ch);
    cudaGetSymbolAddress((void**)&ghall, g_hall);
    cudaGetSymbolAddress((void**)&xh,    g_xh);
    cudaGetSymbolAddress((void**)&hh,    g_hh);
    cudaGetSymbolAddress((void**)&wh,    g_wh);
    cudaGetSymbolAddress((void**)&woh,   g_woh);
    cudaGetSymbolAddress((void**)&gA,    g_Abuf);
    cudaGetSymbolAddress((void**)&gB,    g_Bbuf);
    cudaGetSymbolAddress((void**)&ghb,   g_hb);

    float *hall, *outs;
    long need_both = (long)(Tn + 1) * BD + (long)M * D;
    if ((long)out_size >= need_both) {
        hall = out;
        outs = out + (size_t)(Tn + 1) * BD;
    } else {
        hall = ghall;
        outs = out;
    }

    cudaFuncSetAttribute(gemm_f16<0>, cudaFuncAttributeMaxDynamicSharedMemorySize, GSMEM);
    cudaFuncSetAttribute(gemm_f16<1>, cudaFuncAttributeMaxDynamicSharedMemorySize, GSMEM);

    // Phase 0: r_h flag + one fused fp16 conversion launch
    int n4x = (M * D) / 4;
    int n4w = DD / 4;
    rh_flag_kernel<<<1, 256>>>(r_h, D);
    int n4tot = n4x + 3 * n4w;
    cvt_all<<<(n4tot + 255) / 256, 256>>>(x, W_delta, W_x, W_out,
                                          xh, wh, woh, n4x, n4w);

    // Phase 1: fused delta|cand GEMM (N = 2D, split at D), fp16 outputs
    gemm_f16<0><<<dim3(2 * D / 128, M / 128), 256, GSMEM>>>(
        xh, wh, b_delta, b, gdh, gch, nullptr, D, D, D);

    // Phase 2: scan — parallel chunked fast path (r_h==0) + sequential fallback
    {
        int CHK = 128;
        while (Tn % CHK) CHK >>= 1;
        int NCHK = Tn / CHK;
        if (NCHK > MAX_NCHK) { CHK = Tn / MAX_NCHK; NCHK = MAX_NCHK; }
        dim3 gch2(BD / 512, NCHK);          // 2 lanes per thread
        scan_part1<<<gch2, 256>>>(gdh, gch, gA, gB, BD, CHK);
        scan_part2<<<BD / 256, 256>>>(gA, gB, h0, ghb, hall, BD, NCHK);
        scan_part3<<<gch2, 256>>>(gdh, gch, ghb, hall, hh, BD, CHK);
        scan_seq<<<(BD + 127) / 128, 128>>>(gdh, gch, h0, r_h, hall, hh, Tn, BD, D);
    }

    // Phase 3: output GEMM with fused compete-softmax + silu epilogue
    gemm_f16<1><<<dim3(D / 128, M / 128), 256, GSMEM>>>(
        hh, woh, nullptr, nullptr, outs, nullptr, hh, D, D, 0);
}

// round 11
// speedup vs baseline: 5.4373x; 1.0085x over previous
#include <cuda_runtime.h>
#include <cuda_fp16.h>
#include <math.h>
#include <stdint.h>

// ---------------------------------------------------------------------------
// Scratch (no allocation allowed)
// ---------------------------------------------------------------------------
#define MAX_TBD (2048*16*1024)
#define MAX_HALL ((2048+1)*16*1024)
#define MAX_BD   (16*1024)
#define MAX_NCHK 64
__device__ __half g_dh[MAX_TBD];        // delta fp16 (GEMM0 out)
__device__ __half g_ch[MAX_TBD];        // tanh(cand) fp16 if rh==0, else cand
__device__ float g_hall[MAX_HALL];      // fallback if d_out holds only outs
__device__ __half g_xh[MAX_TBD];        // x fp16
__device__ __half g_hh[MAX_TBD];        // h fp16 (written by scan)
__device__ __half g_wh[2*1024*1024];    // [W_delta ; W_x] fp16
__device__ __half g_woh[1024*1024];     // W_out fp16
__device__ float g_Abuf[MAX_NCHK*MAX_BD];
__device__ float g_Bbuf[MAX_NCHK*MAX_BD];
__device__ float g_hb[MAX_NCHK*MAX_BD];
__device__ int   g_rh_zero;

// ---------------------------------------------------------------------------
// Helpers
// ---------------------------------------------------------------------------
__device__ __forceinline__ uint32_t smem_u32(const void* p) {
    uint32_t a;
    asm("{ .reg .u64 t; cvta.to.shared.u64 t, %1; cvt.u32.u64 %0, t; }" : "=r"(a) : "l"(p));
    return a;
}

#define LDSM_X4(r0, r1, r2, r3, addr) \
    asm volatile("ldmatrix.sync.aligned.m8n8.x4.shared.b16 {%0,%1,%2,%3}, [%4];" \
                 : "=r"(r0), "=r"(r1), "=r"(r2), "=r"(r3) : "r"(addr))

#define MMAF16(c, a, b0, b1) \
    asm volatile("mma.sync.aligned.m16n8k16.row.col.f32.f16.f16.f32 " \
                 "{%0,%1,%2,%3},{%4,%5,%6,%7},{%8,%9},{%0,%1,%2,%3};" \
                 : "+f"((c)[0]), "+f"((c)[1]), "+f"((c)[2]), "+f"((c)[3]) \
                 : "r"((a)[0]), "r"((a)[1]), "r"((a)[2]), "r"((a)[3]), \
                   "r"(b0), "r"(b1))

#define CP16(dst, src) \
    asm volatile("cp.async.cg.shared.global [%0], [%1], 16;" :: "r"(dst), "l"(src) : "memory")
#define CP_COMMIT() asm volatile("cp.async.commit_group;" ::: "memory")
#define CP_WAIT2()  asm volatile("cp.async.wait_group 2;" ::: "memory")
#define CP_WAIT1()  asm volatile("cp.async.wait_group 1;" ::: "memory")
#define CP_WAIT0()  asm volatile("cp.async.wait_group 0;" ::: "memory")

// ---------------------------------------------------------------------------
// One fused fp32 -> fp16 conversion for x + the three weights
// ---------------------------------------------------------------------------
__global__ void cvt_all(const float* __restrict__ x,
                        const float* __restrict__ wd,
                        const float* __restrict__ wx,
                        const float* __restrict__ wo,
                        __half* __restrict__ xh,
                        __half* __restrict__ wh,
                        __half* __restrict__ woh,
                        int n4x, int n4w)
{
    int i = blockIdx.x * blockDim.x + threadIdx.x;
    const float* src;
    __half* dst;
    int off;
    if (i < n4x) {
        src = x; dst = xh; off = i;
    } else {
        int w = i - n4x;
        int which = w / n4w;
        if (which >= 3) return;
        off = w - which * n4w;
        if (which == 0)      { src = wd; dst = wh; }
        else if (which == 1) { src = wx; dst = wh + (size_t)n4w * 4; }
        else                 { src = wo; dst = woh; }
    }
    float4 f = ((const float4*)src)[off];
    ((__half2*)dst)[2*off]   = __halves2half2(__float2half_rn(f.x), __float2half_rn(f.y));
    ((__half2*)dst)[2*off+1] = __halves2half2(__float2half_rn(f.z), __float2half_rn(f.w));
}

// ---------------------------------------------------------------------------
// fp16 1-pass HMMA GEMM: C = epi( A[M,K] @ B[N,K]^T ), fp32 accum.
// CTA 128x128, 8 warps (2x4), warp tile 64x32, BK=32, cp.async 4-stage ring,
// one __syncthreads per chunk. Padded smem rows: 32 fp16 + 16B pad = 80B.
// MODE 0: n0 <  nSplit -> fp16( sigmoid(acc+bias0) ) -> out0 (delta)
//         n0 >= nSplit -> fp16( g_rh_zero ? tanh(acc+bias1) : acc+bias1 ) -> out1
// MODE 1: compete(hsrc fp16) * silu(acc) -> out0 (fp32, streaming store)
// ---------------------------------------------------------------------------
#define STG_B    10240
#define STAGE_SZ 20480
#define NSTAGE   4
#define GSMEM (NSTAGE * STAGE_SZ)

template <int MODE>
__global__ void __launch_bounds__(256, 2) gemm_f16(
    const __half* __restrict__ Ah,
    const __half* __restrict__ Bh,
    const float* __restrict__ bias0,
    const float* __restrict__ bias1,
    void* __restrict__ out0v,
    void* __restrict__ out1v,
    const __half* __restrict__ hsrc,
    int K, int ldC, int nSplit)
{
    extern __shared__ __align__(1024) char smem[];
    const uint32_t sb = smem_u32(smem);
    const int tid = threadIdx.x, wid = tid >> 5, lid = tid & 31;
    const int m0 = blockIdx.y * 128;
    const int n0 = blockIdx.x * 128;

    const size_t aOff = (size_t)(m0 + (tid >> 1)) * K + (size_t)(tid & 1) * 16;
    const size_t bOff = (size_t)(n0 + (tid >> 1)) * K + (size_t)(tid & 1) * 16;
    const uint32_t dOff = (uint32_t)(tid >> 1) * 80 + (uint32_t)(tid & 1) * 32;

    const int wm = wid >> 2, wn = wid & 3;
    const uint32_t aoff = ((uint32_t)((lid & 7) + ((lid >> 3) & 1) * 8) + (uint32_t)wm * 64) * 80
                        + (uint32_t)(lid >> 4) * 16;
    const uint32_t boff = ((uint32_t)((lid & 7) + (lid >> 4) * 8) + (uint32_t)wn * 32) * 80
                        + (uint32_t)((lid >> 3) & 1) * 16;

    float acc[4][4][4];
#pragma unroll
    for (int i = 0; i < 4; ++i)
#pragma unroll
        for (int j = 0; j < 4; ++j)
#pragma unroll
            for (int q = 0; q < 4; ++q) acc[i][j][q] = 0.f;

    const int NCH = K / 32;

    auto issue = [&](int ch, int s) {
        const uint32_t stb = sb + (uint32_t)s * STAGE_SZ;
        const size_t ko = (size_t)ch * 32;
        const __half* a1 = Ah + aOff + ko;
        const __half* b1 = Bh + bOff + ko;
        uint32_t d = stb + dOff;
        CP16(d,            a1);  CP16(d + 16,            a1 + 8);
        CP16(d + STG_B,    b1);  CP16(d + STG_B + 16,    b1 + 8);
    };

    issue(0, 0); CP_COMMIT();
    issue(1, 1); CP_COMMIT();
    issue(2, 2); CP_COMMIT();

#pragma unroll 1
    for (int ch = 0; ch < NCH; ++ch) {
        const int s = ch & (NSTAGE - 1);
        if (ch + 2 < NCH)      CP_WAIT2();
        else if (ch + 1 < NCH) CP_WAIT1();
        else                   CP_WAIT0();
        __syncthreads();
        if (ch + 3 < NCH) { issue(ch + 3, (ch + 3) & (NSTAGE - 1)); CP_COMMIT(); }

        const uint32_t stA = sb + (uint32_t)s * STAGE_SZ;
#pragma unroll
        for (int kk = 0; kk < 2; ++kk) {
            const uint32_t kof = (uint32_t)kk * 32;
            uint32_t bh[4][2];
            LDSM_X4(bh[0][0], bh[0][1], bh[1][0], bh[1][1],
                    stA + STG_B + boff + kof);
            LDSM_X4(bh[2][0], bh[2][1], bh[3][0], bh[3][1],
                    stA + STG_B + boff + 1280 + kof);
            uint32_t ah[4][4];
#pragma unroll
            for (int mi = 0; mi < 4; ++mi)
                LDSM_X4(ah[mi][0], ah[mi][1], ah[mi][2], ah[mi][3],
                        stA + aoff + (uint32_t)mi * 1280 + kof);
#pragma unroll
            for (int mi = 0; mi < 4; ++mi)
#pragma unroll
                for (int nj = 0; nj < 4; ++nj)
                    MMAF16(acc[mi][nj], ah[mi], bh[nj][0], bh[nj][1]);
        }
    }

    // ---- epilogue ----
    const int qr = lid >> 2;       // 0..7
    const int qc = 2 * (lid & 3);  // 0,2,4,6
    const int gcol0 = n0 + wn * 32;

    if (MODE == 0) {
        const int sel = (n0 >= nSplit);
        const int rz = g_rh_zero;
        const float* bias = sel ? bias1 : bias0;
        __half* Cout = sel ? (__half*)out1v : (__half*)out0v;
        const int colBase = gcol0 - sel * nSplit;
        float bv[8];
#pragma unroll
        for (int nj = 0; nj < 4; ++nj) {
            float2 t = *(const float2*)(bias + colBase + nj * 8 + qc);
            bv[2*nj] = t.x; bv[2*nj+1] = t.y;
        }
#pragma unroll
        for (int mi = 0; mi < 4; ++mi) {
            const int r0 = m0 + wm * 64 + mi * 16 + qr;
#pragma unroll
            for (int nj = 0; nj < 4; ++nj) {
                const int c = colBase + nj * 8 + qc;
                float v0 = acc[mi][nj][0] + bv[2*nj];
                float v1 = acc[mi][nj][1] + bv[2*nj+1];
                float v2 = acc[mi][nj][2] + bv[2*nj];
                float v3 = acc[mi][nj][3] + bv[2*nj+1];
                if (!sel) {
                    v0 = 1.f / (1.f + __expf(-v0));
                    v1 = 1.f / (1.f + __expf(-v1));
                    v2 = 1.f / (1.f + __expf(-v2));
                    v3 = 1.f / (1.f + __expf(-v3));
                } else if (rz) {
                    v0 = tanhf(v0); v1 = tanhf(v1);
                    v2 = tanhf(v2); v3 = tanhf(v3);
                }
                *(__half2*)(Cout + (size_t)r0 * ldC + c) =
                    __halves2half2(__float2half_rn(v0), __float2half_rn(v1));
                *(__half2*)(Cout + (size_t)(r0 + 8) * ldC + c) =
                    __halves2half2(__float2half_rn(v2), __float2half_rn(v3));
            }
        }
    } else {
        float* Cout = (float*)out0v;
#pragma unroll
        for (int mi = 0; mi < 4; ++mi) {
            const int r0 = m0 + wm * 64 + mi * 16 + qr;
            const int r1 = r0 + 8;
            float h0v[8], h1v[8];
#pragma unroll
            for (int nj = 0; nj < 4; ++nj) {
                const int c = gcol0 + nj * 8 + qc;
                float2 t0 = __half22float2(*(const __half2*)(hsrc + (size_t)r0 * ldC + c));
                float2 t1 = __half22float2(*(const __half2*)(hsrc + (size_t)r1 * ldC + c));
                h0v[2*nj] = t0.x; h0v[2*nj+1] = t0.y;
                h1v[2*nj] = t1.x; h1v[2*nj+1] = t1.y;
            }
            float mx0 = h0v[0], mx1 = h1v[0];
#pragma unroll
            for (int k = 1; k < 8; ++k) {
                mx0 = fmaxf(mx0, h0v[k]);
                mx1 = fmaxf(mx1, h1v[k]);
            }
            mx0 = fmaxf(mx0, __shfl_xor_sync(0xffffffffu, mx0, 1));
            mx0 = fmaxf(mx0, __shfl_xor_sync(0xffffffffu, mx0, 2));
            mx1 = fmaxf(mx1, __shfl_xor_sync(0xffffffffu, mx1, 1));
            mx1 = fmaxf(mx1, __shfl_xor_sync(0xffffffffu, mx1, 2));
            float s0 = 0.f, s1 = 0.f;
#pragma unroll
            for (int k = 0; k < 8; ++k) {
                h0v[k] = __expf(h0v[k] - mx0); s0 += h0v[k];
                h1v[k] = __expf(h1v[k] - mx1); s1 += h1v[k];
            }
            s0 += __shfl_xor_sync(0xffffffffu, s0, 1);
            s0 += __shfl_xor_sync(0xffffffffu, s0, 2);
            s1 += __shfl_xor_sync(0xffffffffu, s1, 1);
            s1 += __shfl_xor_sync(0xffffffffu, s1, 2);
            const float inv0 = 1.f / s0, inv1 = 1.f / s1;
#pragma unroll
            for (int nj = 0; nj < 4; ++nj) {
                const int c = gcol0 + nj * 8 + qc;
                float y0 = acc[mi][nj][0], y1 = acc[mi][nj][1];
                float y2 = acc[mi][nj][2], y3 = acc[mi][nj][3];
                float v0 = (h0v[2*nj]   * inv0) * (y0 / (1.f + __expf(-y0)));
                float v1 = (h0v[2*nj+1] * inv0) * (y1 / (1.f + __expf(-y1)));
                float v2 = (h1v[2*nj]   * inv1) * (y2 / (1.f + __expf(-y2)));
                float v3 = (h1v[2*nj+1] * inv1) * (y3 / (1.f + __expf(-y3)));
                __stcs((float2*)(Cout + (size_t)r0 * ldC + c), make_float2(v0, v1));
                __stcs((float2*)(Cout + (size_t)r1 * ldC + c), make_float2(v2, v3));
            }
        }
    }
}

// ---------------------------------------------------------------------------
// Scan: parallel fast path when r_h == 0 (linear recurrence), else sequential.
// tc = tanh(cand) is precomputed by GEMM0's epilogue -> scans are pure fma.
// ---------------------------------------------------------------------------
__global__ void rh_flag_kernel(const float* __restrict__ r_h, int D)
{
    int nz = 0;
    for (int i = threadIdx.x; i < D; i += blockDim.x)
        if (r_h[i] != 0.f) nz = 1;
    if (__syncthreads_or(nz)) { if (threadIdx.x == 0) g_rh_zero = 0; }
    else                      { if (threadIdx.x == 0) g_rh_zero = 1; }
}

// Phase 1: per-chunk affine composition (A,B): h_end = A*h_start + B
__global__ void scan_part1(const __half* __restrict__ delta,
                           const __half* __restrict__ tc,
                           float* __restrict__ Abuf,
                           float* __restrict__ Bbuf,
                           int BD, int CHK)
{
    if (!g_rh_zero) return;
    const int l2 = blockIdx.x * blockDim.x + threadIdx.x;
    const int cc = blockIdx.y;
    const int BD2 = BD >> 1;
    const __half2* dp = (const __half2*)delta + (size_t)cc * CHK * BD2 + l2;
    const __half2* cp = (const __half2*)tc    + (size_t)cc * CHK * BD2 + l2;
    float Ax = 1.f, Ay = 1.f, Bx = 0.f, By = 0.f;
#pragma unroll 8
    for (int u = 0; u < CHK; ++u) {
        float2 d = __half22float2(dp[(size_t)u * BD2]);
        float2 t = __half22float2(cp[(size_t)u * BD2]);
        float ax = 1.f - d.x, ay = 1.f - d.y;
        Ax *= ax; Ay *= ay;
        Bx = fmaf(ax, Bx, d.x * t.x);
        By = fmaf(ay, By, d.y * t.y);
    }
    *(float2*)(Abuf + (size_t)cc * BD + 2 * l2) = make_float2(Ax, Ay);
    *(float2*)(Bbuf + (size_t)cc * BD + 2 * l2) = make_float2(Bx, By);
}

// Phase 2: boundary scan across chunks (NCHK steps)
__global__ void scan_part2(const float* __restrict__ Abuf,
                           const float* __restrict__ Bbuf,
                           const float* __restrict__ h0,
                           float* __restrict__ hb,
                           float* __restrict__ h_all,
                           int BD, int NCHK)
{
    if (!g_rh_zero) return;
    const int lane = blockIdx.x * blockDim.x + threadIdx.x;
    float h = h0[lane];
    h_all[lane] = h;
#pragma unroll 4
    for (int cc = 0; cc < NCHK; ++cc) {
        hb[(size_t)cc * BD + lane] = h;
        h = fmaf(Abuf[(size_t)cc * BD + lane], h, Bbuf[(size_t)cc * BD + lane]);
    }
}

// Phase 3: recompute within chunk from boundary, write h_all fp32 + h fp16
__global__ void scan_part3(const __half* __restrict__ delta,
                           const __half* __restrict__ tc,
                           const float* __restrict__ hb,
                           float* __restrict__ h_all,
                           __half* __restrict__ hhi,
                           int BD, int CHK)
{
    if (!g_rh_zero) return;
    const int l2 = blockIdx.x * blockDim.x + threadIdx.x;
    const int cc = blockIdx.y;
    const int BD2 = BD >> 1;
    const __half2* dp = (const __half2*)delta + (size_t)cc * CHK * BD2 + l2;
    const __half2* cp = (const __half2*)tc    + (size_t)cc * CHK * BD2 + l2;
    __half2* hp16 = (__half2*)hhi + (size_t)cc * CHK * BD2 + l2;
    float2* hp32 = (float2*)(h_all + BD) + (size_t)cc * CHK * BD2 + l2;
    float2 h = *(const float2*)(hb + (size_t)cc * BD + 2 * l2);
#pragma unroll 8
    for (int u = 0; u < CHK; ++u) {
        float2 d = __half22float2(__ldcs(dp + (size_t)u * BD2));
        float2 t = __half22float2(__ldcs(cp + (size_t)u * BD2));
        h.x = fmaf(d.x, t.x - h.x, h.x);
        h.y = fmaf(d.y, t.y - h.y, h.y);
        __stcs(hp32 + (size_t)u * BD2, h);
        hp16[(size_t)u * BD2] = __halves2half2(__float2half_rn(h.x), __float2half_rn(h.y));
    }
}

// Fallback: sequential scan (general r_h) — runs only when g_rh_zero == 0
// (in that case g_ch holds RAW cand, not tanh(cand))
__global__ void scan_seq(const __half* __restrict__ delta,
                         const __half* __restrict__ cand,
                         const float* __restrict__ h0,
                         const float* __restrict__ r_h,
                         float* __restrict__ h_all,
                         __half* __restrict__ hhi,
                         int T, int BD, int D)
{
    if (g_rh_zero) return;
    int lane = blockIdx.x * blockDim.x + threadIdx.x;
    if (lane >= BD) return;
    float h = h0[lane];
    float rh = r_h[lane % D];
    h_all[lane] = h;
    for (int t = 0; t < T; ++t) {
        float d = __half2float(delta[(size_t)t * BD + lane]);
        float c = __half2float(cand[(size_t)t * BD + lane]);
        float cv = tanhf(fmaf(rh, h, c));
        h = fmaf(d, cv - h, h);
        h_all[BD + (size_t)t * BD + lane] = h;
        hhi[(size_t)t * BD + lane] = __float2half_rn(h);
    }
}

// ---------------------------------------------------------------------------
extern "C" void kernel_launch(void* const* d_in, const int* in_sizes, int n_in,
                              void* d_out, int out_size)
{
    const float* x       = (const float*)d_in[0];
    const float* h0      = (const float*)d_in[1];
    const float* W_x     = (const float*)d_in[2];
    const float* r_h     = (const float*)d_in[3];
    const float* b       = (const float*)d_in[4];
    const float* W_delta = (const float*)d_in[5];
    const float* b_delta = (const float*)d_in[6];
    const float* W_out   = (const float*)d_in[7];
    float* out = (float*)d_out;

    int D  = (int)(sqrt((double)in_sizes[2]) + 0.5);
    int Bn = in_sizes[1] / D;
    int Tn = in_sizes[0] / (Bn * D);
    int BD = Bn * D;
    int M  = Tn * Bn;
    int DD = D * D;

    float *ghall, *gA, *gB, *ghb;
    __half *gdh, *gch, *xh, *hh, *wh, *woh;
    cudaGetSymbolAddress((void**)&gdh,   g_dh);
    cudaGetSymbolAddress((void**)&gch,   g_ch);
    cudaGetSymbolAddress((void**)&ghall, g_hall);
    cudaGetSymbolAddress((void**)&xh,    g_xh);
    cudaGetSymbolAddress((void**)&hh,    g_hh);
    cudaGetSymbolAddress((void**)&wh,    g_wh);
    cudaGetSymbolAddress((void**)&woh,   g_woh);
    cudaGetSymbolAddress((void**)&gA,    g_Abuf);
    cudaGetSymbolAddress((void**)&gB,    g_Bbuf);
    cudaGetSymbolAddress((void**)&ghb,   g_hb);

    float *hall, *outs;
    long need_both = (long)(Tn + 1) * BD + (long)M * D;
    if ((long)out_size >= need_both) {
        hall = out;
        outs = out + (size_t)(Tn + 1) * BD;
    } else {
        hall = ghall;
        outs = out;
    }

    cudaFuncSetAttribute(gemm_f16<0>, cudaFuncAttributeMaxDynamicSharedMemorySize, GSMEM);
    cudaFuncSetAttribute(gemm_f16<1>, cudaFuncAttributeMaxDynamicSharedMemorySize, GSMEM);

    // Phase 0: r_h flag (must precede GEMM0 epilogue's tanh decision) + cvt
    int n4x = (M * D) / 4;
    int n4w = DD / 4;
    rh_flag_kernel<<<1, 256>>>(r_h, D);
    int n4tot = n4x + 3 * n4w;
    cvt_all<<<(n4tot + 255) / 256, 256>>>(x, W_delta, W_x, W_out,
                                          xh, wh, woh, n4x, n4w);

    // Phase 1: fused delta|tc GEMM (N = 2D, split at D), fp16 outputs
    gemm_f16<0><<<dim3(2 * D / 128, M / 128), 256, GSMEM>>>(
        xh, wh, b_delta, b, gdh, gch, nullptr, D, D, D);

    // Phase 2: scan — parallel chunked fast path (r_h==0) + sequential fallback
    {
        int CHK = 64;
        while (Tn % CHK) CHK >>= 1;
        int NCHK = Tn / CHK;
        if (NCHK > MAX_NCHK) { CHK = Tn / MAX_NCHK; NCHK = MAX_NCHK; }
        dim3 gch2(BD / 512, NCHK);          // 2 lanes per thread
        scan_part1<<<gch2, 256>>>(gdh, gch, gA, gB, BD, CHK);
        scan_part2<<<BD / 256, 256>>>(gA, gB, h0, ghb, hall, BD, NCHK);
        scan_part3<<<gch2, 256>>>(gdh, gch, ghb, hall, hh, BD, CHK);
        scan_seq<<<(BD + 127) / 128, 128>>>(gdh, gch, h0, r_h, hall, hh, Tn, BD, D);
    }

    // Phase 3: output GEMM with fused compete-softmax + silu epilogue
    gemm_f16<1><<<dim3(D / 128, M / 128), 256, GSMEM>>>(
        hh, woh, nullptr, nullptr, outs, nullptr, hh, D, D, 0);
}